// round 9
// baseline (speedup 1.0000x reference)
#include <cuda_runtime.h>

typedef unsigned long long ull;

#define NN 50000
#define DD 128
#define EE 1600000
#define TWO_N (2*NN)
#define SCAN_B 512
#define NSB ((TWO_N + SCAN_B - 1)/SCAN_B)
#define TILE_R 64
#define NBLK ((NN + TILE_R - 1)/TILE_R)          // 782 fc blocks
#define AGG_NPB 8                                 // agg nodes per block (8 warps... 256 thr)
#define AGG_BLOCKS ((NN + AGG_NPB - 1)/AGG_NPB)   // 6250
#define COMB_BLOCKS (NBLK + AGG_BLOCKS)           // 7032
#define STRIPE 9                                  // every 9th block is fc
#define PAD 68
#define RMP 132
#define GT 256

// ---------------- f32x2 packed-math helpers ----------------
__device__ __forceinline__ ull bcast2(float x) {
    ull r; asm("mov.b64 %0, {%1,%1};" : "=l"(r) : "f"(x)); return r;
}
__device__ __forceinline__ ull pack2f(float lo, float hi) {
    ull r; asm("mov.b64 %0, {%1,%2};" : "=l"(r) : "f"(lo), "f"(hi)); return r;
}
__device__ __forceinline__ void ffma2(ull& d, ull a, ull b) {
    asm("fma.rn.f32x2 %0, %1, %2, %0;" : "+l"(d) : "l"(a), "l"(b));
}
__device__ __forceinline__ float2 unpack2(ull v) {
    float2 f; asm("mov.b64 {%0,%1}, %2;" : "=f"(f.x), "=f"(f.y) : "l"(v)); return f;
}

// ---------------- scratch ----------------
__device__ int   g_cnt[TWO_N];
__device__ int   g_off[TWO_N + 1];
__device__ int   g_bsum[NSB];
__device__ int   g_col[2*EE];
__device__ float g_ua[NN*DD];   // ua, later reused as phase-A partial
__device__ float g_ub[NN*DD];

// ---------------- CSR construction ----------------
__global__ void zero_cnt_kernel() {
    int i = blockIdx.x*blockDim.x + threadIdx.x;
    if (i < TWO_N) g_cnt[i] = 0;
}

__global__ void hist_kernel(const int* __restrict__ et, const int* __restrict__ ex) {
    int i = blockIdx.x*blockDim.x + threadIdx.x;
    if (i < EE) {
        atomicAdd(&g_cnt[et[EE + i]], 1);
        atomicAdd(&g_cnt[NN + ex[EE + i]], 1);
    }
}

__global__ void scan1_kernel() {
    __shared__ int s[SCAN_B];
    int i = blockIdx.x*SCAN_B + threadIdx.x;
    int v = (i < TWO_N) ? g_cnt[i] : 0;
    s[threadIdx.x] = v;
    __syncthreads();
    #pragma unroll
    for (int d = 1; d < SCAN_B; d <<= 1) {
        int tv = (threadIdx.x >= d) ? s[threadIdx.x - d] : 0;
        __syncthreads();
        s[threadIdx.x] += tv;
        __syncthreads();
    }
    if (i < TWO_N) g_off[i + 1] = s[threadIdx.x];
    if (threadIdx.x == SCAN_B - 1) g_bsum[blockIdx.x] = s[SCAN_B - 1];
}

__global__ void scan2_kernel() {
    __shared__ int s[256];
    int v = (threadIdx.x < NSB) ? g_bsum[threadIdx.x] : 0;
    s[threadIdx.x] = v;
    __syncthreads();
    #pragma unroll
    for (int d = 1; d < 256; d <<= 1) {
        int tv = (threadIdx.x >= d) ? s[threadIdx.x - d] : 0;
        __syncthreads();
        s[threadIdx.x] += tv;
        __syncthreads();
    }
    if (threadIdx.x < NSB) g_bsum[threadIdx.x] = s[threadIdx.x] - v;
}

__global__ void scan3_kernel() {
    int i = blockIdx.x*blockDim.x + threadIdx.x;
    if (i == 0) { g_off[0] = 0; g_cnt[0] = 0; }
    else if (i <= TWO_N) {
        int v = g_off[i] + g_bsum[(i - 1) / SCAN_B];
        g_off[i] = v;
        if (i < TWO_N) g_cnt[i] = v;
    }
}

__global__ void fill_kernel(const int* __restrict__ et, const int* __restrict__ ex) {
    int i = blockIdx.x*blockDim.x + threadIdx.x;
    if (i < EE) {
        int p = atomicAdd(&g_cnt[et[EE + i]], 1);
        g_col[p] = et[i];
        int q = atomicAdd(&g_cnt[NN + ex[EE + i]], 1);
        g_col[q] = ex[i];
    }
}

// ================= GEMM building blocks (256 threads: 8 rows x 4 cols) =========
__device__ __forceinline__ void gemm_layer_T(const float* __restrict__ sIn,
                                             const float* __restrict__ sW,
                                             int rb, int tc, ull acc[4][4]) {
    #pragma unroll 2
    for (int k = 0; k < 128; k++) {
        ulonglong2 A0 = *(const ulonglong2*)&sIn[k*PAD + rb];
        ulonglong2 A1 = *(const ulonglong2*)&sIn[k*PAD + rb + 4];
        float4 bv = *(const float4*)(sW + k*128 + tc*4);
        ull b0 = bcast2(bv.x), b1 = bcast2(bv.y), b2 = bcast2(bv.z), b3 = bcast2(bv.w);
        ull ap0 = A0.x, ap1 = A0.y, ap2 = A1.x, ap3 = A1.y;
        ffma2(acc[0][0], ap0, b0); ffma2(acc[0][1], ap0, b1); ffma2(acc[0][2], ap0, b2); ffma2(acc[0][3], ap0, b3);
        ffma2(acc[1][0], ap1, b0); ffma2(acc[1][1], ap1, b1); ffma2(acc[1][2], ap1, b2); ffma2(acc[1][3], ap1, b3);
        ffma2(acc[2][0], ap2, b0); ffma2(acc[2][1], ap2, b1); ffma2(acc[2][2], ap2, b2); ffma2(acc[2][3], ap2, b3);
        ffma2(acc[3][0], ap3, b0); ffma2(acc[3][1], ap3, b1); ffma2(acc[3][2], ap3, b2); ffma2(acc[3][3], ap3, b3);
    }
}

__device__ __forceinline__ void gemm_layer_rm(const float* __restrict__ sIn,
                                              const float* __restrict__ sW,
                                              int rb, int tc, ull acc[4][4]) {
    const float* base = sIn + rb*RMP;
    #pragma unroll 2
    for (int k = 0; k < 128; k++) {
        float h0 = base[0*RMP + k], h1 = base[1*RMP + k];
        float h2 = base[2*RMP + k], h3 = base[3*RMP + k];
        float h4 = base[4*RMP + k], h5 = base[5*RMP + k];
        float h6 = base[6*RMP + k], h7 = base[7*RMP + k];
        ull ap0 = pack2f(h0, h1), ap1 = pack2f(h2, h3);
        ull ap2 = pack2f(h4, h5), ap3 = pack2f(h6, h7);
        float4 bv = *(const float4*)(sW + k*128 + tc*4);
        ull b0 = bcast2(bv.x), b1 = bcast2(bv.y), b2 = bcast2(bv.z), b3 = bcast2(bv.w);
        ffma2(acc[0][0], ap0, b0); ffma2(acc[0][1], ap0, b1); ffma2(acc[0][2], ap0, b2); ffma2(acc[0][3], ap0, b3);
        ffma2(acc[1][0], ap1, b0); ffma2(acc[1][1], ap1, b1); ffma2(acc[1][2], ap1, b2); ffma2(acc[1][3], ap1, b3);
        ffma2(acc[2][0], ap2, b0); ffma2(acc[2][1], ap2, b1); ffma2(acc[2][2], ap2, b2); ffma2(acc[2][3], ap2, b3);
        ffma2(acc[3][0], ap3, b0); ffma2(acc[3][1], ap3, b1); ffma2(acc[3][2], ap3, b2); ffma2(acc[3][3], ap3, b3);
    }
}

__device__ __forceinline__ void zero_acc(ull acc[4][4]) {
    #pragma unroll
    for (int p = 0; p < 4; p++)
        #pragma unroll
        for (int c = 0; c < 4; c++) acc[p][c] = 0ull;
}

__device__ __forceinline__ void relu_store_rm(const ull acc[4][4], float4 bv,
                                              float* __restrict__ sOut, int rb, int tc) {
    #pragma unroll
    for (int p = 0; p < 4; p++) {
        float2 v0 = unpack2(acc[p][0]);
        float2 v1 = unpack2(acc[p][1]);
        float2 v2 = unpack2(acc[p][2]);
        float2 v3 = unpack2(acc[p][3]);
        float4 lo, hi;
        lo.x = fmaxf(v0.x + bv.x, 0.f); hi.x = fmaxf(v0.y + bv.x, 0.f);
        lo.y = fmaxf(v1.x + bv.y, 0.f); hi.y = fmaxf(v1.y + bv.y, 0.f);
        lo.z = fmaxf(v2.x + bv.z, 0.f); hi.z = fmaxf(v2.y + bv.z, 0.f);
        lo.w = fmaxf(v3.x + bv.w, 0.f); hi.w = fmaxf(v3.y + bv.w, 0.f);
        *(float4*)&sOut[(rb + 2*p)*RMP + tc*4]     = lo;
        *(float4*)&sOut[(rb + 2*p + 1)*RMP + tc*4] = hi;
    }
}

__device__ __forceinline__ void load_tileT(float* __restrict__ sAT,
                                           const float* __restrict__ A,
                                           int row0, int tid) {
    #pragma unroll
    for (int idx = tid; idx < TILE_R*128; idx += GT) {
        int r = idx >> 7, k = idx & 127;
        int row = row0 + r;
        sAT[k*PAD + r] = (row < NN) ? A[(size_t)row*128 + k] : 0.f;
    }
}

__device__ __forceinline__ void copy_w(float* __restrict__ dst,
                                       const float* __restrict__ src, int tid) {
    const float4* s4 = (const float4*)src;
    float4* d4 = (float4*)dst;
    #pragma unroll
    for (int i = tid; i < 4096; i += GT) d4[i] = s4[i];
}

#define SMEM_G_FLOATS (16384 + 128*PAD)
#define SMEM_G_BYTES  (SMEM_G_FLOATS * 4)

// ---------------- agg device body: warp per destination node, unroll 4 --------
__device__ __forceinline__ void agg_body(int aggb, const float* __restrict__ x,
                                         const float* __restrict__ t,
                                         float* __restrict__ ua, float* __restrict__ ub) {
    int warp = aggb*AGG_NPB + (threadIdx.x >> 5);
    int lane = threadIdx.x & 31;
    if (warp >= NN) return;
    const float4* t4 = (const float4*)t;
    const float4* x4 = (const float4*)x;

    float4 base = t4[warp*32 + lane];
    float4 aA = base, aB = base;

    {
        int e = g_off[warp], eE = g_off[warp + 1];
        for (; e + 3 < eE; e += 4) {
            int s0 = g_col[e], s1 = g_col[e+1], s2 = g_col[e+2], s3 = g_col[e+3];
            float4 v0 = t4[s0*32 + lane];
            float4 v1 = t4[s1*32 + lane];
            float4 v2 = t4[s2*32 + lane];
            float4 v3 = t4[s3*32 + lane];
            aA.x += v0.x + v1.x + v2.x + v3.x;
            aA.y += v0.y + v1.y + v2.y + v3.y;
            aA.z += v0.z + v1.z + v2.z + v3.z;
            aA.w += v0.w + v1.w + v2.w + v3.w;
        }
        for (; e < eE; e++) {
            int s0 = g_col[e];
            float4 v0 = t4[s0*32 + lane];
            aA.x += v0.x; aA.y += v0.y; aA.z += v0.z; aA.w += v0.w;
        }
    }
    {
        int e = g_off[NN + warp], eE = g_off[NN + warp + 1];
        for (; e + 3 < eE; e += 4) {
            int s0 = g_col[e], s1 = g_col[e+1], s2 = g_col[e+2], s3 = g_col[e+3];
            float4 v0 = x4[s0*32 + lane];
            float4 v1 = x4[s1*32 + lane];
            float4 v2 = x4[s2*32 + lane];
            float4 v3 = x4[s3*32 + lane];
            aB.x += v0.x + v1.x + v2.x + v3.x;
            aB.y += v0.y + v1.y + v2.y + v3.y;
            aB.z += v0.z + v1.z + v2.z + v3.z;
            aB.w += v0.w + v1.w + v2.w + v3.w;
        }
        for (; e < eE; e++) {
            int s0 = g_col[e];
            float4 v0 = x4[s0*32 + lane];
            aB.x += v0.x; aB.y += v0.y; aB.z += v0.z; aB.w += v0.w;
        }
    }

    ((float4*)ua)[warp*32 + lane] = aA;
    ((float4*)ub)[warp*32 + lane] = aB;
}

// ---------------- fc_x device body ----------------
__device__ __forceinline__ void fcx_body(int blk, const float* __restrict__ X,
                                         const float* __restrict__ W1, const float* __restrict__ B1,
                                         const float* __restrict__ W2, const float* __restrict__ B2,
                                         float* __restrict__ OUT, float* sm) {
    float* sW  = sm;            // staged weight
    float* sRG = sm + 16384;    // A^T [128][PAD], then H [64][RMP]

    const int tid = threadIdx.x;
    const int tc = tid & 31;
    const int rb = (tid >> 5) * 8;
    const int row0 = blk * TILE_R;

    float4 vb1 = ((const float4*)B1)[tc];
    float4 vb2 = ((const float4*)B2)[tc];

    copy_w(sW, W1, tid);
    load_tileT(sRG, X, row0, tid);
    __syncthreads();

    ull acc[4][4];
    zero_acc(acc);
    gemm_layer_T(sRG, sW, rb, tc, acc);
    __syncthreads();

    relu_store_rm(acc, vb1, sRG, rb, tc);
    copy_w(sW, W2, tid);
    __syncthreads();

    zero_acc(acc);
    gemm_layer_rm(sRG, sW, rb, tc, acc);

    #pragma unroll
    for (int p = 0; p < 4; p++) {
        float2 v0 = unpack2(acc[p][0]);
        float2 v1 = unpack2(acc[p][1]);
        float2 v2 = unpack2(acc[p][2]);
        float2 v3 = unpack2(acc[p][3]);
        #pragma unroll
        for (int q = 0; q < 2; q++) {
            int row = row0 + rb + 2*p + q;
            if (row < NN) {
                float4 xv = ((const float4*)X)[(size_t)row*32 + tc];
                float4 o;
                o.x = xv.x + (q ? v0.y : v0.x) + vb2.x;
                o.y = xv.y + (q ? v1.y : v1.x) + vb2.y;
                o.z = xv.z + (q ? v2.y : v2.x) + vb2.z;
                o.w = xv.w + (q ? v3.y : v3.x) + vb2.w;
                ((float4*)OUT)[(size_t)row*32 + tc] = o;
            }
        }
    }
}

// ================= combined fc_x + agg launch (striped) =================
__global__ __launch_bounds__(GT, 2) void fcx_agg_kernel(
    const float* __restrict__ X, const float* __restrict__ T,
    const float* __restrict__ W1, const float* __restrict__ B1,
    const float* __restrict__ W2, const float* __restrict__ B2,
    float* __restrict__ OUTX,
    float* __restrict__ ua, float* __restrict__ ub)
{
    extern __shared__ float sm[];
    int bid = blockIdx.x;
    if (bid % STRIPE == 0) {
        fcx_body(bid / STRIPE, X, W1, B1, W2, B2, OUTX, sm);
    } else {
        agg_body(bid - bid/STRIPE - 1, X, T, ua, ub);
    }
}

// ================= fused t-branch (unchanged from R6) =================
__global__ __launch_bounds__(GT, 2) void fused_t_kernel(
    float* __restrict__ ua,
    const float* __restrict__ ub,
    const float* __restrict__ t,
    const float* __restrict__ W1a, const float* __restrict__ b1a,
    const float* __restrict__ W2a, const float* __restrict__ b2a,
    const float* __restrict__ W1b, const float* __restrict__ b1b,
    const float* __restrict__ W2b, const float* __restrict__ b2b,
    const float* __restrict__ Wo,  const float* __restrict__ bo,
    const float* __restrict__ lng, const float* __restrict__ lnb,
    float* __restrict__ OUT)
{
    extern __shared__ float sm[];
    float* sW  = sm;
    float* sRG = sm + 16384;

    const int tid = threadIdx.x;
    const int tc  = tid & 31;
    const int rb  = (tid >> 5) * 8;
    const int row0 = blockIdx.x * TILE_R;

    float4 vb1a = ((const float4*)b1a)[tc];
    float4 vb2a = ((const float4*)b2a)[tc];
    float4 vb1b = ((const float4*)b1b)[tc];
    float4 vb2b = ((const float4*)b2b)[tc];
    float4 vbo  = ((const float4*)bo)[tc];
    float4 vg   = ((const float4*)lng)[tc];
    float4 vbe  = ((const float4*)lnb)[tc];

    ull acc[4][4];

    // ---- phase A: gin_a(ua); partial = t + ga + b2a -> g_ua ----
    copy_w(sW, W1a, tid);
    load_tileT(sRG, ua, row0, tid);
    __syncthreads();

    zero_acc(acc);
    gemm_layer_T(sRG, sW, rb, tc, acc);
    __syncthreads();

    relu_store_rm(acc, vb1a, sRG, rb, tc);
    copy_w(sW, W2a, tid);
    __syncthreads();

    zero_acc(acc);
    gemm_layer_rm(sRG, sW, rb, tc, acc);

    #pragma unroll
    for (int p = 0; p < 4; p++) {
        float2 v0 = unpack2(acc[p][0]);
        float2 v1 = unpack2(acc[p][1]);
        float2 v2 = unpack2(acc[p][2]);
        float2 v3 = unpack2(acc[p][3]);
        #pragma unroll
        for (int q = 0; q < 2; q++) {
            int row = row0 + rb + 2*p + q;
            if (row < NN) {
                float4 tv = ((const float4*)t)[(size_t)row*32 + tc];
                float4 o;
                o.x = tv.x + (q ? v0.y : v0.x) + vb2a.x;
                o.y = tv.y + (q ? v1.y : v1.x) + vb2a.y;
                o.z = tv.z + (q ? v2.y : v2.x) + vb2a.z;
                o.w = tv.w + (q ? v3.y : v3.x) + vb2a.w;
                ((float4*)ua)[(size_t)row*32 + tc] = o;
            }
        }
    }
    __syncthreads();

    // ---- phase B: gin_b(ub); t2 = relu(partial + gb + b2b) -> sRG row-major ----
    copy_w(sW, W1b, tid);
    load_tileT(sRG, ub, row0, tid);
    __syncthreads();

    zero_acc(acc);
    gemm_layer_T(sRG, sW, rb, tc, acc);
    __syncthreads();

    relu_store_rm(acc, vb1b, sRG, rb, tc);
    copy_w(sW, W2b, tid);
    __syncthreads();

    zero_acc(acc);
    gemm_layer_rm(sRG, sW, rb, tc, acc);
    __syncthreads();

    #pragma unroll
    for (int p = 0; p < 4; p++) {
        float2 v0 = unpack2(acc[p][0]);
        float2 v1 = unpack2(acc[p][1]);
        float2 v2 = unpack2(acc[p][2]);
        float2 v3 = unpack2(acc[p][3]);
        #pragma unroll
        for (int q = 0; q < 2; q++) {
            int r = rb + 2*p + q;
            int row = row0 + r;
            float4 pv = make_float4(0.f, 0.f, 0.f, 0.f);
            if (row < NN) pv = ((const float4*)ua)[(size_t)row*32 + tc];
            float4 o;
            o.x = fmaxf(pv.x + (q ? v0.y : v0.x) + vb2b.x, 0.f);
            o.y = fmaxf(pv.y + (q ? v1.y : v1.x) + vb2b.y, 0.f);
            o.z = fmaxf(pv.z + (q ? v2.y : v2.x) + vb2b.z, 0.f);
            o.w = fmaxf(pv.w + (q ? v3.y : v3.x) + vb2b.w, 0.f);
            *(float4*)&sRG[r*RMP + tc*4] = o;
        }
    }
    copy_w(sW, Wo, tid);
    __syncthreads();

    // ---- phase O: z = relu(t2@Wo + bo) in regs; LN via warp shuffles ----
    zero_acc(acc);
    gemm_layer_rm(sRG, sW, rb, tc, acc);

    float z8[8][4];
    #pragma unroll
    for (int p = 0; p < 4; p++) {
        float2 v0 = unpack2(acc[p][0]);
        float2 v1 = unpack2(acc[p][1]);
        float2 v2 = unpack2(acc[p][2]);
        float2 v3 = unpack2(acc[p][3]);
        z8[2*p  ][0] = fmaxf(v0.x + vbo.x, 0.f);
        z8[2*p+1][0] = fmaxf(v0.y + vbo.x, 0.f);
        z8[2*p  ][1] = fmaxf(v1.x + vbo.y, 0.f);
        z8[2*p+1][1] = fmaxf(v1.y + vbo.y, 0.f);
        z8[2*p  ][2] = fmaxf(v2.x + vbo.z, 0.f);
        z8[2*p+1][2] = fmaxf(v2.y + vbo.z, 0.f);
        z8[2*p  ][3] = fmaxf(v3.x + vbo.w, 0.f);
        z8[2*p+1][3] = fmaxf(v3.y + vbo.w, 0.f);
    }

    #pragma unroll
    for (int r = 0; r < 8; r++) {
        float s  = z8[r][0] + z8[r][1] + z8[r][2] + z8[r][3];
        float sq = z8[r][0]*z8[r][0] + z8[r][1]*z8[r][1]
                 + z8[r][2]*z8[r][2] + z8[r][3]*z8[r][3];
        #pragma unroll
        for (int d = 16; d > 0; d >>= 1) {
            s  += __shfl_xor_sync(0xffffffffu, s,  d);
            sq += __shfl_xor_sync(0xffffffffu, sq, d);
        }
        float m = s * (1.f/128.f);
        float var = sq * (1.f/128.f) - m*m;
        float rstd = rsqrtf(var + 1e-5f);
        int row = row0 + rb + r;
        if (row < NN) {
            float4 t2v = *(const float4*)&sRG[(rb + r)*RMP + tc*4];
            float4 o;
            o.x = t2v.x + (z8[r][0] - m)*rstd*vg.x + vbe.x;
            o.y = t2v.y + (z8[r][1] - m)*rstd*vg.y + vbe.y;
            o.z = t2v.z + (z8[r][2] - m)*rstd*vg.z + vbe.z;
            o.w = t2v.w + (z8[r][3] - m)*rstd*vg.w + vbe.w;
            ((float4*)OUT)[(size_t)row*32 + tc] = o;
        }
    }
}

// ---------------- launcher ----------------
extern "C" void kernel_launch(void* const* d_in, const int* in_sizes, int n_in,
                              void* d_out, int out_size) {
    const float* x   = (const float*)d_in[0];
    const float* t   = (const float*)d_in[1];
    const int*   et  = (const int*)d_in[2];
    const int*   ex  = (const int*)d_in[3];
    const float* W1a = (const float*)d_in[4];
    const float* b1a = (const float*)d_in[5];
    const float* W2a = (const float*)d_in[6];
    const float* b2a = (const float*)d_in[7];
    const float* W1b = (const float*)d_in[8];
    const float* b1b = (const float*)d_in[9];
    const float* W2b = (const float*)d_in[10];
    const float* b2b = (const float*)d_in[11];
    const float* Wo  = (const float*)d_in[12];
    const float* bo  = (const float*)d_in[13];
    const float* lng = (const float*)d_in[14];
    const float* lnb = (const float*)d_in[15];
    const float* Wf1 = (const float*)d_in[16];
    const float* bf1 = (const float*)d_in[17];
    const float* Wf2 = (const float*)d_in[18];
    const float* bf2 = (const float*)d_in[19];
    float* out = (float*)d_out;

    float *pua, *pub;
    cudaGetSymbolAddress((void**)&pua, g_ua);
    cudaGetSymbolAddress((void**)&pub, g_ub);

    cudaFuncSetAttribute(fcx_agg_kernel, cudaFuncAttributeMaxDynamicSharedMemorySize, SMEM_G_BYTES);
    cudaFuncSetAttribute(fused_t_kernel, cudaFuncAttributeMaxDynamicSharedMemorySize, SMEM_G_BYTES);

    // CSR build
    zero_cnt_kernel<<<(TWO_N + 1023)/1024, 1024>>>();
    hist_kernel<<<(EE + 255)/256, 256>>>(et, ex);
    scan1_kernel<<<NSB, SCAN_B>>>();
    scan2_kernel<<<1, 256>>>();
    scan3_kernel<<<(TWO_N + 1 + 255)/256, 256>>>();
    fill_kernel<<<(EE + 255)/256, 256>>>(et, ex);

    // combined: fc_x (compute) striped with agg (L2 gather) — overlap resources
    fcx_agg_kernel<<<COMB_BLOCKS, GT, SMEM_G_BYTES>>>(x, t, Wf1, bf1, Wf2, bf2,
                                                      out, pua, pub);

    // fused t-branch: gin_a + gin_b + t2 + out Linear + LayerNorm + residual
    fused_t_kernel<<<NBLK, GT, SMEM_G_BYTES>>>(pua, pub, t,
        W1a, b1a, W2a, b2a, W1b, b1b, W2b, b2b,
        Wo, bo, lng, lnb, out + (size_t)NN*DD);
}

// round 10
// speedup vs baseline: 1.0910x; 1.0910x over previous
#include <cuda_runtime.h>

typedef unsigned long long ull;

#define NN 50000
#define DD 128
#define EE 1600000
#define TWO_N (2*NN)
#define SCAN_B 512
#define NSB ((TWO_N + SCAN_B - 1)/SCAN_B)
#define TILE_R 64
#define NBLK ((NN + TILE_R - 1)/TILE_R)
#define PAD 68
#define RMP 132
#define GT 256

// ---------------- f32x2 packed-math helpers ----------------
__device__ __forceinline__ ull bcast2(float x) {
    ull r; asm("mov.b64 %0, {%1,%1};" : "=l"(r) : "f"(x)); return r;
}
__device__ __forceinline__ ull pack2f(float lo, float hi) {
    ull r; asm("mov.b64 %0, {%1,%2};" : "=l"(r) : "f"(lo), "f"(hi)); return r;
}
__device__ __forceinline__ void ffma2(ull& d, ull a, ull b) {
    asm("fma.rn.f32x2 %0, %1, %2, %0;" : "+l"(d) : "l"(a), "l"(b));
}
__device__ __forceinline__ float2 unpack2(ull v) {
    float2 f; asm("mov.b64 {%0,%1}, %2;" : "=f"(f.x), "=f"(f.y) : "l"(v)); return f;
}

// ---------------- scratch ----------------
__device__ int   g_cnt[TWO_N];
__device__ int   g_off[TWO_N + 1];
__device__ int   g_bsum[NSB];
__device__ int   g_col[2*EE];
__device__ float g_ua[NN*DD];   // ua, later reused as phase-A partial
__device__ float g_ub[NN*DD];

// ---------------- CSR construction ----------------
__global__ void zero_cnt_kernel() {
    int i = blockIdx.x*blockDim.x + threadIdx.x;
    if (i < TWO_N) g_cnt[i] = 0;
}

__global__ void hist_kernel(const int* __restrict__ et, const int* __restrict__ ex) {
    int i = blockIdx.x*blockDim.x + threadIdx.x;
    if (i < EE) {
        atomicAdd(&g_cnt[et[EE + i]], 1);
        atomicAdd(&g_cnt[NN + ex[EE + i]], 1);
    }
}

__global__ void scan1_kernel() {
    __shared__ int s[SCAN_B];
    int i = blockIdx.x*SCAN_B + threadIdx.x;
    int v = (i < TWO_N) ? g_cnt[i] : 0;
    s[threadIdx.x] = v;
    __syncthreads();
    #pragma unroll
    for (int d = 1; d < SCAN_B; d <<= 1) {
        int tv = (threadIdx.x >= d) ? s[threadIdx.x - d] : 0;
        __syncthreads();
        s[threadIdx.x] += tv;
        __syncthreads();
    }
    if (i < TWO_N) g_off[i + 1] = s[threadIdx.x];
    if (threadIdx.x == SCAN_B - 1) g_bsum[blockIdx.x] = s[SCAN_B - 1];
}

__global__ void scan2_kernel() {
    __shared__ int s[256];
    int v = (threadIdx.x < NSB) ? g_bsum[threadIdx.x] : 0;
    s[threadIdx.x] = v;
    __syncthreads();
    #pragma unroll
    for (int d = 1; d < 256; d <<= 1) {
        int tv = (threadIdx.x >= d) ? s[threadIdx.x - d] : 0;
        __syncthreads();
        s[threadIdx.x] += tv;
        __syncthreads();
    }
    if (threadIdx.x < NSB) g_bsum[threadIdx.x] = s[threadIdx.x] - v;
}

__global__ void scan3_kernel() {
    int i = blockIdx.x*blockDim.x + threadIdx.x;
    if (i == 0) { g_off[0] = 0; g_cnt[0] = 0; }
    else if (i <= TWO_N) {
        int v = g_off[i] + g_bsum[(i - 1) / SCAN_B];
        g_off[i] = v;
        if (i < TWO_N) g_cnt[i] = v;
    }
}

__global__ void fill_kernel(const int* __restrict__ et, const int* __restrict__ ex) {
    int i = blockIdx.x*blockDim.x + threadIdx.x;
    if (i < EE) {
        int p = atomicAdd(&g_cnt[et[EE + i]], 1);
        g_col[p] = et[i];
        int q = atomicAdd(&g_cnt[NN + ex[EE + i]], 1);
        g_col[q] = ex[i];
    }
}

// ---------------- aggregation: warp per destination node (standalone, no smem,
// low regs -> high occupancy for L2 latency hiding) ----------------
__global__ void agg_kernel(const float* __restrict__ x, const float* __restrict__ t,
                           float* __restrict__ ua, float* __restrict__ ub) {
    int warp = (blockIdx.x*blockDim.x + threadIdx.x) >> 5;
    int lane = threadIdx.x & 31;
    if (warp >= NN) return;
    const float4* t4 = (const float4*)t;
    const float4* x4 = (const float4*)x;

    float4 base = t4[warp*32 + lane];
    float4 aA = base, aB = base;

    {
        int e = g_off[warp], eE = g_off[warp + 1];
        for (; e + 3 < eE; e += 4) {
            int s0 = g_col[e], s1 = g_col[e+1], s2 = g_col[e+2], s3 = g_col[e+3];
            float4 v0 = t4[s0*32 + lane];
            float4 v1 = t4[s1*32 + lane];
            float4 v2 = t4[s2*32 + lane];
            float4 v3 = t4[s3*32 + lane];
            aA.x += v0.x + v1.x + v2.x + v3.x;
            aA.y += v0.y + v1.y + v2.y + v3.y;
            aA.z += v0.z + v1.z + v2.z + v3.z;
            aA.w += v0.w + v1.w + v2.w + v3.w;
        }
        for (; e < eE; e++) {
            int s0 = g_col[e];
            float4 v0 = t4[s0*32 + lane];
            aA.x += v0.x; aA.y += v0.y; aA.z += v0.z; aA.w += v0.w;
        }
    }
    {
        int e = g_off[NN + warp], eE = g_off[NN + warp + 1];
        for (; e + 3 < eE; e += 4) {
            int s0 = g_col[e], s1 = g_col[e+1], s2 = g_col[e+2], s3 = g_col[e+3];
            float4 v0 = x4[s0*32 + lane];
            float4 v1 = x4[s1*32 + lane];
            float4 v2 = x4[s2*32 + lane];
            float4 v3 = x4[s3*32 + lane];
            aB.x += v0.x + v1.x + v2.x + v3.x;
            aB.y += v0.y + v1.y + v2.y + v3.y;
            aB.z += v0.z + v1.z + v2.z + v3.z;
            aB.w += v0.w + v1.w + v2.w + v3.w;
        }
        for (; e < eE; e++) {
            int s0 = g_col[e];
            float4 v0 = x4[s0*32 + lane];
            aB.x += v0.x; aB.y += v0.y; aB.z += v0.z; aB.w += v0.w;
        }
    }

    ((float4*)ua)[warp*32 + lane] = aA;
    ((float4*)ub)[warp*32 + lane] = aB;
}

// ================= GEMM building blocks (256 threads: 8 rows x 4 cols) =========
__device__ __forceinline__ void gemm_layer_T(const float* __restrict__ sIn,
                                             const float* __restrict__ sW,
                                             int rb, int tc, ull acc[4][4]) {
    #pragma unroll 2
    for (int k = 0; k < 128; k++) {
        ulonglong2 A0 = *(const ulonglong2*)&sIn[k*PAD + rb];
        ulonglong2 A1 = *(const ulonglong2*)&sIn[k*PAD + rb + 4];
        float4 bv = *(const float4*)(sW + k*128 + tc*4);
        ull b0 = bcast2(bv.x), b1 = bcast2(bv.y), b2 = bcast2(bv.z), b3 = bcast2(bv.w);
        ull ap0 = A0.x, ap1 = A0.y, ap2 = A1.x, ap3 = A1.y;
        ffma2(acc[0][0], ap0, b0); ffma2(acc[0][1], ap0, b1); ffma2(acc[0][2], ap0, b2); ffma2(acc[0][3], ap0, b3);
        ffma2(acc[1][0], ap1, b0); ffma2(acc[1][1], ap1, b1); ffma2(acc[1][2], ap1, b2); ffma2(acc[1][3], ap1, b3);
        ffma2(acc[2][0], ap2, b0); ffma2(acc[2][1], ap2, b1); ffma2(acc[2][2], ap2, b2); ffma2(acc[2][3], ap2, b3);
        ffma2(acc[3][0], ap3, b0); ffma2(acc[3][1], ap3, b1); ffma2(acc[3][2], ap3, b2); ffma2(acc[3][3], ap3, b3);
    }
}

__device__ __forceinline__ void gemm_layer_rm(const float* __restrict__ sIn,
                                              const float* __restrict__ sW,
                                              int rb, int tc, ull acc[4][4]) {
    const float* base = sIn + rb*RMP;
    #pragma unroll 2
    for (int k = 0; k < 128; k++) {
        float h0 = base[0*RMP + k], h1 = base[1*RMP + k];
        float h2 = base[2*RMP + k], h3 = base[3*RMP + k];
        float h4 = base[4*RMP + k], h5 = base[5*RMP + k];
        float h6 = base[6*RMP + k], h7 = base[7*RMP + k];
        ull ap0 = pack2f(h0, h1), ap1 = pack2f(h2, h3);
        ull ap2 = pack2f(h4, h5), ap3 = pack2f(h6, h7);
        float4 bv = *(const float4*)(sW + k*128 + tc*4);
        ull b0 = bcast2(bv.x), b1 = bcast2(bv.y), b2 = bcast2(bv.z), b3 = bcast2(bv.w);
        ffma2(acc[0][0], ap0, b0); ffma2(acc[0][1], ap0, b1); ffma2(acc[0][2], ap0, b2); ffma2(acc[0][3], ap0, b3);
        ffma2(acc[1][0], ap1, b0); ffma2(acc[1][1], ap1, b1); ffma2(acc[1][2], ap1, b2); ffma2(acc[1][3], ap1, b3);
        ffma2(acc[2][0], ap2, b0); ffma2(acc[2][1], ap2, b1); ffma2(acc[2][2], ap2, b2); ffma2(acc[2][3], ap2, b3);
        ffma2(acc[3][0], ap3, b0); ffma2(acc[3][1], ap3, b1); ffma2(acc[3][2], ap3, b2); ffma2(acc[3][3], ap3, b3);
    }
}

__device__ __forceinline__ void zero_acc(ull acc[4][4]) {
    #pragma unroll
    for (int p = 0; p < 4; p++)
        #pragma unroll
        for (int c = 0; c < 4; c++) acc[p][c] = 0ull;
}

__device__ __forceinline__ void relu_store_rm(const ull acc[4][4], float4 bv,
                                              float* __restrict__ sOut, int rb, int tc) {
    #pragma unroll
    for (int p = 0; p < 4; p++) {
        float2 v0 = unpack2(acc[p][0]);
        float2 v1 = unpack2(acc[p][1]);
        float2 v2 = unpack2(acc[p][2]);
        float2 v3 = unpack2(acc[p][3]);
        float4 lo, hi;
        lo.x = fmaxf(v0.x + bv.x, 0.f); hi.x = fmaxf(v0.y + bv.x, 0.f);
        lo.y = fmaxf(v1.x + bv.y, 0.f); hi.y = fmaxf(v1.y + bv.y, 0.f);
        lo.z = fmaxf(v2.x + bv.z, 0.f); hi.z = fmaxf(v2.y + bv.z, 0.f);
        lo.w = fmaxf(v3.x + bv.w, 0.f); hi.w = fmaxf(v3.y + bv.w, 0.f);
        *(float4*)&sOut[(rb + 2*p)*RMP + tc*4]     = lo;
        *(float4*)&sOut[(rb + 2*p + 1)*RMP + tc*4] = hi;
    }
}

__device__ __forceinline__ void load_tileT(float* __restrict__ sAT,
                                           const float* __restrict__ A,
                                           int row0, int tid) {
    #pragma unroll
    for (int idx = tid; idx < TILE_R*128; idx += GT) {
        int r = idx >> 7, k = idx & 127;
        int row = row0 + r;
        sAT[k*PAD + r] = (row < NN) ? A[(size_t)row*128 + k] : 0.f;
    }
}

__device__ __forceinline__ void copy_w(float* __restrict__ dst,
                                       const float* __restrict__ src, int tid) {
    const float4* s4 = (const float4*)src;
    float4* d4 = (float4*)dst;
    #pragma unroll
    for (int i = tid; i < 4096; i += GT) d4[i] = s4[i];
}

#define SMEM_G_FLOATS (16384 + 128*PAD)
#define SMEM_G_BYTES  (SMEM_G_FLOATS * 4)

// ================= fc_x: x_out = x + relu(x@Wf1+bf1)@Wf2 + bf2 =================
__global__ __launch_bounds__(GT, 2) void fc_x_kernel(
    const float* __restrict__ X,
    const float* __restrict__ W1, const float* __restrict__ B1,
    const float* __restrict__ W2, const float* __restrict__ B2,
    float* __restrict__ OUT)
{
    extern __shared__ float sm[];
    float* sW  = sm;
    float* sRG = sm + 16384;

    const int tid = threadIdx.x;
    const int tc = tid & 31;
    const int rb = (tid >> 5) * 8;
    const int row0 = blockIdx.x * TILE_R;

    float4 vb1 = ((const float4*)B1)[tc];
    float4 vb2 = ((const float4*)B2)[tc];

    copy_w(sW, W1, tid);
    load_tileT(sRG, X, row0, tid);
    __syncthreads();

    ull acc[4][4];
    zero_acc(acc);
    gemm_layer_T(sRG, sW, rb, tc, acc);
    __syncthreads();

    relu_store_rm(acc, vb1, sRG, rb, tc);
    copy_w(sW, W2, tid);
    __syncthreads();

    zero_acc(acc);
    gemm_layer_rm(sRG, sW, rb, tc, acc);

    #pragma unroll
    for (int p = 0; p < 4; p++) {
        float2 v0 = unpack2(acc[p][0]);
        float2 v1 = unpack2(acc[p][1]);
        float2 v2 = unpack2(acc[p][2]);
        float2 v3 = unpack2(acc[p][3]);
        #pragma unroll
        for (int q = 0; q < 2; q++) {
            int row = row0 + rb + 2*p + q;
            if (row < NN) {
                float4 xv = ((const float4*)X)[(size_t)row*32 + tc];
                float4 o;
                o.x = xv.x + (q ? v0.y : v0.x) + vb2.x;
                o.y = xv.y + (q ? v1.y : v1.x) + vb2.y;
                o.z = xv.z + (q ? v2.y : v2.x) + vb2.z;
                o.w = xv.w + (q ? v3.y : v3.x) + vb2.w;
                ((float4*)OUT)[(size_t)row*32 + tc] = o;
            }
        }
    }
}

// ================= fused t-branch =================
__global__ __launch_bounds__(GT, 2) void fused_t_kernel(
    float* __restrict__ ua,
    const float* __restrict__ ub,
    const float* __restrict__ t,
    const float* __restrict__ W1a, const float* __restrict__ b1a,
    const float* __restrict__ W2a, const float* __restrict__ b2a,
    const float* __restrict__ W1b, const float* __restrict__ b1b,
    const float* __restrict__ W2b, const float* __restrict__ b2b,
    const float* __restrict__ Wo,  const float* __restrict__ bo,
    const float* __restrict__ lng, const float* __restrict__ lnb,
    float* __restrict__ OUT)
{
    extern __shared__ float sm[];
    float* sW  = sm;
    float* sRG = sm + 16384;

    const int tid = threadIdx.x;
    const int tc  = tid & 31;
    const int rb  = (tid >> 5) * 8;
    const int row0 = blockIdx.x * TILE_R;

    float4 vb1a = ((const float4*)b1a)[tc];
    float4 vb2a = ((const float4*)b2a)[tc];
    float4 vb1b = ((const float4*)b1b)[tc];
    float4 vb2b = ((const float4*)b2b)[tc];
    float4 vbo  = ((const float4*)bo)[tc];
    float4 vg   = ((const float4*)lng)[tc];
    float4 vbe  = ((const float4*)lnb)[tc];

    ull acc[4][4];

    // ---- phase A: gin_a(ua); partial = t + ga + b2a -> g_ua ----
    copy_w(sW, W1a, tid);
    load_tileT(sRG, ua, row0, tid);
    __syncthreads();

    zero_acc(acc);
    gemm_layer_T(sRG, sW, rb, tc, acc);
    __syncthreads();

    relu_store_rm(acc, vb1a, sRG, rb, tc);
    copy_w(sW, W2a, tid);
    __syncthreads();

    zero_acc(acc);
    gemm_layer_rm(sRG, sW, rb, tc, acc);

    #pragma unroll
    for (int p = 0; p < 4; p++) {
        float2 v0 = unpack2(acc[p][0]);
        float2 v1 = unpack2(acc[p][1]);
        float2 v2 = unpack2(acc[p][2]);
        float2 v3 = unpack2(acc[p][3]);
        #pragma unroll
        for (int q = 0; q < 2; q++) {
            int row = row0 + rb + 2*p + q;
            if (row < NN) {
                float4 tv = ((const float4*)t)[(size_t)row*32 + tc];
                float4 o;
                o.x = tv.x + (q ? v0.y : v0.x) + vb2a.x;
                o.y = tv.y + (q ? v1.y : v1.x) + vb2a.y;
                o.z = tv.z + (q ? v2.y : v2.x) + vb2a.z;
                o.w = tv.w + (q ? v3.y : v3.x) + vb2a.w;
                ((float4*)ua)[(size_t)row*32 + tc] = o;
            }
        }
    }
    __syncthreads();

    // ---- phase B: gin_b(ub); t2 = relu(partial + gb + b2b) -> sRG row-major ----
    copy_w(sW, W1b, tid);
    load_tileT(sRG, ub, row0, tid);
    __syncthreads();

    zero_acc(acc);
    gemm_layer_T(sRG, sW, rb, tc, acc);
    __syncthreads();

    relu_store_rm(acc, vb1b, sRG, rb, tc);
    copy_w(sW, W2b, tid);
    __syncthreads();

    zero_acc(acc);
    gemm_layer_rm(sRG, sW, rb, tc, acc);
    __syncthreads();

    #pragma unroll
    for (int p = 0; p < 4; p++) {
        float2 v0 = unpack2(acc[p][0]);
        float2 v1 = unpack2(acc[p][1]);
        float2 v2 = unpack2(acc[p][2]);
        float2 v3 = unpack2(acc[p][3]);
        #pragma unroll
        for (int q = 0; q < 2; q++) {
            int r = rb + 2*p + q;
            int row = row0 + r;
            float4 pv = make_float4(0.f, 0.f, 0.f, 0.f);
            if (row < NN) pv = ((const float4*)ua)[(size_t)row*32 + tc];
            float4 o;
            o.x = fmaxf(pv.x + (q ? v0.y : v0.x) + vb2b.x, 0.f);
            o.y = fmaxf(pv.y + (q ? v1.y : v1.x) + vb2b.y, 0.f);
            o.z = fmaxf(pv.z + (q ? v2.y : v2.x) + vb2b.z, 0.f);
            o.w = fmaxf(pv.w + (q ? v3.y : v3.x) + vb2b.w, 0.f);
            *(float4*)&sRG[r*RMP + tc*4] = o;
        }
    }
    copy_w(sW, Wo, tid);
    __syncthreads();

    // ---- phase O: z = relu(t2@Wo + bo) in regs; LN via warp shuffles ----
    zero_acc(acc);
    gemm_layer_rm(sRG, sW, rb, tc, acc);

    float z8[8][4];
    #pragma unroll
    for (int p = 0; p < 4; p++) {
        float2 v0 = unpack2(acc[p][0]);
        float2 v1 = unpack2(acc[p][1]);
        float2 v2 = unpack2(acc[p][2]);
        float2 v3 = unpack2(acc[p][3]);
        z8[2*p  ][0] = fmaxf(v0.x + vbo.x, 0.f);
        z8[2*p+1][0] = fmaxf(v0.y + vbo.x, 0.f);
        z8[2*p  ][1] = fmaxf(v1.x + vbo.y, 0.f);
        z8[2*p+1][1] = fmaxf(v1.y + vbo.y, 0.f);
        z8[2*p  ][2] = fmaxf(v2.x + vbo.z, 0.f);
        z8[2*p+1][2] = fmaxf(v2.y + vbo.z, 0.f);
        z8[2*p  ][3] = fmaxf(v3.x + vbo.w, 0.f);
        z8[2*p+1][3] = fmaxf(v3.y + vbo.w, 0.f);
    }

    #pragma unroll
    for (int r = 0; r < 8; r++) {
        float s  = z8[r][0] + z8[r][1] + z8[r][2] + z8[r][3];
        float sq = z8[r][0]*z8[r][0] + z8[r][1]*z8[r][1]
                 + z8[r][2]*z8[r][2] + z8[r][3]*z8[r][3];
        #pragma unroll
        for (int d = 16; d > 0; d >>= 1) {
            s  += __shfl_xor_sync(0xffffffffu, s,  d);
            sq += __shfl_xor_sync(0xffffffffu, sq, d);
        }
        float m = s * (1.f/128.f);
        float var = sq * (1.f/128.f) - m*m;
        float rstd = rsqrtf(var + 1e-5f);
        int row = row0 + rb + r;
        if (row < NN) {
            float4 t2v = *(const float4*)&sRG[(rb + r)*RMP + tc*4];
            float4 o;
            o.x = t2v.x + (z8[r][0] - m)*rstd*vg.x + vbe.x;
            o.y = t2v.y + (z8[r][1] - m)*rstd*vg.y + vbe.y;
            o.z = t2v.z + (z8[r][2] - m)*rstd*vg.z + vbe.z;
            o.w = t2v.w + (z8[r][3] - m)*rstd*vg.w + vbe.w;
            ((float4*)OUT)[(size_t)row*32 + tc] = o;
        }
    }
}

// ---------------- launcher: forked-stream graph (fc_x ∥ CSR+agg) ----------------
extern "C" void kernel_launch(void* const* d_in, const int* in_sizes, int n_in,
                              void* d_out, int out_size) {
    const float* x   = (const float*)d_in[0];
    const float* t   = (const float*)d_in[1];
    const int*   et  = (const int*)d_in[2];
    const int*   ex  = (const int*)d_in[3];
    const float* W1a = (const float*)d_in[4];
    const float* b1a = (const float*)d_in[5];
    const float* W2a = (const float*)d_in[6];
    const float* b2a = (const float*)d_in[7];
    const float* W1b = (const float*)d_in[8];
    const float* b1b = (const float*)d_in[9];
    const float* W2b = (const float*)d_in[10];
    const float* b2b = (const float*)d_in[11];
    const float* Wo  = (const float*)d_in[12];
    const float* bo  = (const float*)d_in[13];
    const float* lng = (const float*)d_in[14];
    const float* lnb = (const float*)d_in[15];
    const float* Wf1 = (const float*)d_in[16];
    const float* bf1 = (const float*)d_in[17];
    const float* Wf2 = (const float*)d_in[18];
    const float* bf2 = (const float*)d_in[19];
    float* out = (float*)d_out;

    float *pua, *pub;
    cudaGetSymbolAddress((void**)&pua, g_ua);
    cudaGetSymbolAddress((void**)&pub, g_ub);

    cudaFuncSetAttribute(fc_x_kernel, cudaFuncAttributeMaxDynamicSharedMemorySize, SMEM_G_BYTES);
    cudaFuncSetAttribute(fused_t_kernel, cudaFuncAttributeMaxDynamicSharedMemorySize, SMEM_G_BYTES);

    // Fork a side stream for the independent fc_x branch (graph-capture safe:
    // fork and join via events; no sync, no allocation).
    cudaStream_t side;
    cudaStreamCreateWithFlags(&side, cudaStreamNonBlocking);
    cudaEvent_t eFork, eJoin;
    cudaEventCreateWithFlags(&eFork, cudaEventDisableTiming);
    cudaEventCreateWithFlags(&eJoin, cudaEventDisableTiming);

    cudaEventRecord(eFork, 0);
    cudaStreamWaitEvent(side, eFork, 0);

    // branch B (side stream): fc_x — depends only on x/Wf*, writes out[0:NN*DD)
    fc_x_kernel<<<NBLK, GT, SMEM_G_BYTES, side>>>(x, Wf1, bf1, Wf2, bf2, out);
    cudaEventRecord(eJoin, side);

    // branch A (main stream): CSR build + aggregation
    zero_cnt_kernel<<<(TWO_N + 1023)/1024, 1024>>>();
    hist_kernel<<<(EE + 255)/256, 256>>>(et, ex);
    scan1_kernel<<<NSB, SCAN_B>>>();
    scan2_kernel<<<1, 256>>>();
    scan3_kernel<<<(TWO_N + 1 + 255)/256, 256>>>();
    fill_kernel<<<(EE + 255)/256, 256>>>(et, ex);
    agg_kernel<<<(NN + 7)/8, 256>>>(x, t, pua, pub);

    // join: fused_t starts after both branches
    cudaStreamWaitEvent(0, eJoin, 0);
    fused_t_kernel<<<NBLK, GT, SMEM_G_BYTES>>>(pua, pub, t,
        W1a, b1a, W2a, b2a, W1b, b1b, W2b, b2b,
        Wo, bo, lng, lnb, out + (size_t)NN*DD);

    cudaEventDestroy(eFork);
    cudaEventDestroy(eJoin);
    cudaStreamDestroy(side);
}

// round 12
// speedup vs baseline: 1.4733x; 1.3504x over previous
#include <cuda_runtime.h>

typedef unsigned long long ull;
typedef unsigned int u32;

#define NN 50000
#define DD 128
#define EE 1600000
#define TWO_N (2*NN)
#define SCAN_B 512
#define NSB ((TWO_N + SCAN_B - 1)/SCAN_B)
#define MT 128
#define NBLK_MM ((NN + MT - 1)/MT)   // 391
#define MMT 256                       // threads (8 warps)

// smem map (bytes): A frags hi/lo, B frags, biases
#define S_AHI 0
#define S_ALO 32768
#define S_B   65536
#define S_BIAS 98304
#define SMEM_MM 102400

// ---------------- scratch ----------------
__device__ int   g_cnt[TWO_N];
__device__ int   g_off[TWO_N + 1];
__device__ int   g_bsum[NSB];
__device__ int   g_col[2*EE];
__device__ float g_ua[NN*DD];
__device__ float g_ub[NN*DD];

// ---------------- bf16 helpers ----------------
// pack two floats to bf16x2: low half = lo, high half = hi
__device__ __forceinline__ u32 pkbf(float lo, float hi) {
    u32 r; asm("cvt.rn.bf16x2.f32 %0, %1, %2;" : "=r"(r) : "f"(hi), "f"(lo)); return r;
}
__device__ __forceinline__ float bf_lo(u32 p) { return __uint_as_float(p << 16); }
__device__ __forceinline__ float bf_hi(u32 p) { return __uint_as_float(p & 0xffff0000u); }

#define MMA4(d, a0, a1, a2, a3, b0, b1) \
    asm volatile("mma.sync.aligned.m16n8k16.row.col.f32.bf16.bf16.f32 " \
        "{%0,%1,%2,%3}, {%4,%5,%6,%7}, {%8,%9}, {%0,%1,%2,%3};" \
        : "+f"((d)[0]), "+f"((d)[1]), "+f"((d)[2]), "+f"((d)[3]) \
        : "r"(a0), "r"(a1), "r"(a2), "r"(a3), "r"(b0), "r"(b1))

// ---------------- fragment staging ----------------
// A frags: [ks 8][mt 8][lane 32][reg 4] u32 (bf16x2). Element (r,k):
//   ks=k>>4, mt=r>>4, lane=(r&7)*4 + ((k&15)>>1 & 3)... staged by k-pairs below.
__device__ __forceinline__ void stage_A(u32* sAhi, u32* sAlo, const float* A, int row0) {
    for (int idx = threadIdx.x; idx < 128*64; idx += MMT) {
        int r = idx >> 6, j = idx & 63;        // cols 2j, 2j+1
        int row = row0 + r;
        float v0 = 0.f, v1 = 0.f;
        if (row < NN) {
            float2 vv = *(const float2*)(A + (size_t)row*128 + 2*j);
            v0 = vv.x; v1 = vv.y;
        }
        u32 hp = pkbf(v0, v1);
        u32 lp = pkbf(v0 - bf_lo(hp), v1 - bf_hi(hp));
        int ks = j >> 3;
        int reg = ((r >> 3) & 1) | ((j & 4) ? 2 : 0);
        int ln  = (r & 7)*4 + (j & 3);
        int mt  = r >> 4;
        int o = ((ks*8 + mt)*32 + ln)*4 + reg;
        sAhi[o] = hp; sAlo[o] = lp;
    }
}

// B frags for one N-half: [ks 8][nt 8][lane 32][4]: {bhi0,bhi1,blo0,blo1}
__device__ __forceinline__ void stage_W(u32* sB, const float* __restrict__ W, int half) {
    for (int idx = threadIdx.x; idx < 2048; idx += MMT) {
        int ln = idx & 31, nt = (idx >> 5) & 7, ks = idx >> 8;
        int g = ln >> 2, c = ln & 3;
        int n = half*64 + nt*8 + g;
        int k0 = ks*16 + 2*c;
        float w00 = W[(size_t)k0*128 + n];
        float w01 = W[(size_t)(k0+1)*128 + n];
        float w10 = W[(size_t)(k0+8)*128 + n];
        float w11 = W[(size_t)(k0+9)*128 + n];
        u32 bh0 = pkbf(w00, w01);
        u32 bh1 = pkbf(w10, w11);
        u32 bl0 = pkbf(w00 - bf_lo(bh0), w01 - bf_hi(bh0));
        u32 bl1 = pkbf(w10 - bf_lo(bh1), w11 - bf_hi(bh1));
        uint4 v = make_uint4(bh0, bh1, bl0, bl1);
        *(uint4*)(sB + idx*4) = v;
    }
}

// mma over one N-half: acc[nt][4], 3-term bf16 split
__device__ __forceinline__ void mma_half(const u32* sAhi, const u32* sAlo, const u32* sB,
                                         int wid, int lane, float acc[8][4]) {
    #pragma unroll
    for (int nt = 0; nt < 8; nt++)
        #pragma unroll
        for (int q = 0; q < 4; q++) acc[nt][q] = 0.f;
    #pragma unroll
    for (int ks = 0; ks < 8; ks++) {
        uint4 ah = *(const uint4*)(sAhi + ((ks*8 + wid)*32 + lane)*4);
        uint4 al = *(const uint4*)(sAlo + ((ks*8 + wid)*32 + lane)*4);
        #pragma unroll
        for (int nt = 0; nt < 8; nt++) {
            uint4 b = *(const uint4*)(sB + ((ks*8 + nt)*32 + lane)*4);
            MMA4(acc[nt], ah.x, ah.y, ah.z, ah.w, b.x, b.y);
            MMA4(acc[nt], al.x, al.y, al.z, al.w, b.x, b.y);
            MMA4(acc[nt], ah.x, ah.y, ah.z, ah.w, b.z, b.w);
        }
    }
}

// full layer: both halves into acc0/acc1 (W is [128][128] gmem row-major k x n)
__device__ __forceinline__ void layer(u32* sAhi, u32* sAlo, u32* sB,
                                      const float* __restrict__ W,
                                      int wid, int lane,
                                      float acc0[8][4], float acc1[8][4]) {
    __syncthreads();
    stage_W(sB, W, 0);
    __syncthreads();
    mma_half(sAhi, sAlo, sB, wid, lane, acc0);
    __syncthreads();
    stage_W(sB, W, 1);
    __syncthreads();
    mma_half(sAhi, sAlo, sB, wid, lane, acc1);
}

// H-write: A frags <- relu(acc + bias)   (own-mtile only; no sync needed)
__device__ __forceinline__ void write_H(u32* sAhi, u32* sAlo,
                                        float acc0[8][4], float acc1[8][4],
                                        const float* bias, int wid, int lane) {
    int g = lane >> 2, c = lane & 3;
    #pragma unroll
    for (int half = 0; half < 2; half++) {
        float (*acc)[4] = half ? acc1 : acc0;
        #pragma unroll
        for (int nt = 0; nt < 8; nt++) {
            int col = half*64 + nt*8 + 2*c;
            float b0 = bias[col], b1 = bias[col+1];
            int j = col >> 1;
            int ks = j >> 3;
            int ln = g*4 + (j & 3);
            int base = ((ks*8 + wid)*32 + ln)*4 + ((j & 4) ? 2 : 0);
            #pragma unroll
            for (int pr = 0; pr < 2; pr++) {
                float v0 = fmaxf(acc[nt][pr*2]   + b0, 0.f);
                float v1 = fmaxf(acc[nt][pr*2+1] + b1, 0.f);
                u32 hp = pkbf(v0, v1);
                u32 lp = pkbf(v0 - bf_lo(hp), v1 - bf_hi(hp));
                sAhi[base + pr] = hp;
                sAlo[base + pr] = lp;
            }
        }
    }
}

// ================= fc_x: x + relu(x@Wf1+bf1)@Wf2 + bf2 =================
__global__ __launch_bounds__(MMT, 2) void fc_x_mm(
    const float* __restrict__ X,
    const float* __restrict__ W1, const float* __restrict__ B1,
    const float* __restrict__ W2, const float* __restrict__ B2,
    float* __restrict__ OUT)
{
    extern __shared__ char smc[];
    u32* sAhi = (u32*)(smc + S_AHI);
    u32* sAlo = (u32*)(smc + S_ALO);
    u32* sB   = (u32*)(smc + S_B);
    float* sb1 = (float*)(smc + S_BIAS);
    float* sb2 = (float*)(smc + S_BIAS + 512);

    const int tid = threadIdx.x;
    const int wid = tid >> 5, lane = tid & 31;
    const int row0 = blockIdx.x * MT;
    if (tid < 128) { sb1[tid] = B1[tid]; sb2[tid] = B2[tid]; }
    stage_A(sAhi, sAlo, X, row0);

    float acc0[8][4], acc1[8][4];
    layer(sAhi, sAlo, sB, W1, wid, lane, acc0, acc1);
    write_H(sAhi, sAlo, acc0, acc1, sb1, wid, lane);
    layer(sAhi, sAlo, sB, W2, wid, lane, acc0, acc1);

    int g = lane >> 2, c = lane & 3;
    int r0 = row0 + wid*16 + g;
    #pragma unroll
    for (int half = 0; half < 2; half++) {
        float (*acc)[4] = half ? acc1 : acc0;
        #pragma unroll
        for (int nt = 0; nt < 8; nt++) {
            int col = half*64 + nt*8 + 2*c;
            float b0 = sb2[col], b1 = sb2[col+1];
            #pragma unroll
            for (int pr = 0; pr < 2; pr++) {
                int row = r0 + pr*8;
                if (row < NN) {
                    float2 xv = *(const float2*)(X + (size_t)row*128 + col);
                    float2 o;
                    o.x = xv.x + acc[nt][pr*2]   + b0;
                    o.y = xv.y + acc[nt][pr*2+1] + b1;
                    *(float2*)(OUT + (size_t)row*128 + col) = o;
                }
            }
        }
    }
}

// ================= fused t-branch =================
__global__ __launch_bounds__(MMT, 2) void fused_t_mm(
    float* __restrict__ ua, const float* __restrict__ ub, const float* __restrict__ t,
    const float* __restrict__ W1a, const float* __restrict__ b1a,
    const float* __restrict__ W2a, const float* __restrict__ b2a,
    const float* __restrict__ W1b, const float* __restrict__ b1b,
    const float* __restrict__ W2b, const float* __restrict__ b2b,
    const float* __restrict__ Wo,  const float* __restrict__ bo,
    const float* __restrict__ lng, const float* __restrict__ lnb,
    float* __restrict__ OUT)
{
    extern __shared__ char smc[];
    u32* sAhi = (u32*)(smc + S_AHI);
    u32* sAlo = (u32*)(smc + S_ALO);
    u32* sB   = (u32*)(smc + S_B);
    float* s_b1a = (float*)(smc + S_BIAS);
    float* s_b2a = (float*)(smc + S_BIAS + 512);
    float* s_b1b = (float*)(smc + S_BIAS + 1024);
    float* s_b2b = (float*)(smc + S_BIAS + 1536);
    float* s_bo  = (float*)(smc + S_BIAS + 2048);
    float* s_g   = (float*)(smc + S_BIAS + 2560);
    float* s_be  = (float*)(smc + S_BIAS + 3072);

    const int tid = threadIdx.x;
    const int wid = tid >> 5, lane = tid & 31;
    const int g = lane >> 2, c = lane & 3;
    const int row0 = blockIdx.x * MT;
    const int r0 = row0 + wid*16 + g;

    if (tid < 128) {
        s_b1a[tid] = b1a[tid]; s_b2a[tid] = b2a[tid];
        s_b1b[tid] = b1b[tid]; s_b2b[tid] = b2b[tid];
        s_bo[tid]  = bo[tid];  s_g[tid]   = lng[tid]; s_be[tid] = lnb[tid];
    }
    stage_A(sAhi, sAlo, ua, row0);

    float acc0[8][4], acc1[8][4];

    // ---- gin_a ----
    layer(sAhi, sAlo, sB, W1a, wid, lane, acc0, acc1);
    write_H(sAhi, sAlo, acc0, acc1, s_b1a, wid, lane);
    layer(sAhi, sAlo, sB, W2a, wid, lane, acc0, acc1);

    // partial = t + ga + b2a -> g_ua
    #pragma unroll
    for (int half = 0; half < 2; half++) {
        float (*acc)[4] = half ? acc1 : acc0;
        #pragma unroll
        for (int nt = 0; nt < 8; nt++) {
            int col = half*64 + nt*8 + 2*c;
            float b0 = s_b2a[col], b1 = s_b2a[col+1];
            #pragma unroll
            for (int pr = 0; pr < 2; pr++) {
                int row = r0 + pr*8;
                if (row < NN) {
                    float2 tv = *(const float2*)(t + (size_t)row*128 + col);
                    float2 o;
                    o.x = tv.x + acc[nt][pr*2]   + b0;
                    o.y = tv.y + acc[nt][pr*2+1] + b1;
                    *(float2*)(ua + (size_t)row*128 + col) = o;
                }
            }
        }
    }

    // ---- gin_b ----
    __syncthreads();
    stage_A(sAhi, sAlo, ub, row0);
    layer(sAhi, sAlo, sB, W1b, wid, lane, acc0, acc1);
    write_H(sAhi, sAlo, acc0, acc1, s_b1b, wid, lane);
    layer(sAhi, sAlo, sB, W2b, wid, lane, acc0, acc1);

    // t2 = relu(partial + gb + b2b) -> A frags (input of Wo layer)
    #pragma unroll
    for (int half = 0; half < 2; half++) {
        float (*acc)[4] = half ? acc1 : acc0;
        #pragma unroll
        for (int nt = 0; nt < 8; nt++) {
            int col = half*64 + nt*8 + 2*c;
            float b0 = s_b2b[col], b1 = s_b2b[col+1];
            int j = col >> 1;
            int ks = j >> 3;
            int ln = g*4 + (j & 3);
            int base = ((ks*8 + wid)*32 + ln)*4 + ((j & 4) ? 2 : 0);
            #pragma unroll
            for (int pr = 0; pr < 2; pr++) {
                int row = r0 + pr*8;
                float p0 = 0.f, p1 = 0.f;
                if (row < NN) {
                    float2 pv = *(const float2*)(ua + (size_t)row*128 + col);
                    p0 = pv.x; p1 = pv.y;
                }
                float v0 = fmaxf(p0 + acc[nt][pr*2]   + b0, 0.f);
                float v1 = fmaxf(p1 + acc[nt][pr*2+1] + b1, 0.f);
                u32 hp = pkbf(v0, v1);
                u32 lp = pkbf(v0 - bf_lo(hp), v1 - bf_hi(hp));
                sAhi[base + pr] = hp;
                sAlo[base + pr] = lp;
            }
        }
    }

    // ---- out branch: z = relu(t2@Wo+bo); OUT = t2 + LN(z) ----
    layer(sAhi, sAlo, sB, Wo, wid, lane, acc0, acc1);

    // per-row sums across the 4 lanes sharing g (lanes g*4..g*4+3)
    float s0 = 0.f, q0 = 0.f, s1 = 0.f, q1 = 0.f;
    #pragma unroll
    for (int half = 0; half < 2; half++) {
        float (*acc)[4] = half ? acc1 : acc0;
        #pragma unroll
        for (int nt = 0; nt < 8; nt++) {
            int col = half*64 + nt*8 + 2*c;
            float b0 = s_bo[col], b1 = s_bo[col+1];
            float z00 = fmaxf(acc[nt][0] + b0, 0.f);
            float z01 = fmaxf(acc[nt][1] + b1, 0.f);
            float z10 = fmaxf(acc[nt][2] + b0, 0.f);
            float z11 = fmaxf(acc[nt][3] + b1, 0.f);
            s0 += z00 + z01; q0 += z00*z00 + z01*z01;
            s1 += z10 + z11; q1 += z10*z10 + z11*z11;
        }
    }
    #pragma unroll
    for (int d = 1; d <= 2; d <<= 1) {
        s0 += __shfl_xor_sync(0xffffffffu, s0, d);
        q0 += __shfl_xor_sync(0xffffffffu, q0, d);
        s1 += __shfl_xor_sync(0xffffffffu, s1, d);
        q1 += __shfl_xor_sync(0xffffffffu, q1, d);
    }
    float m0 = s0*(1.f/128.f), m1 = s1*(1.f/128.f);
    float rs0 = rsqrtf(q0*(1.f/128.f) - m0*m0 + 1e-5f);
    float rs1 = rsqrtf(q1*(1.f/128.f) - m1*m1 + 1e-5f);

    #pragma unroll
    for (int half = 0; half < 2; half++) {
        float (*acc)[4] = half ? acc1 : acc0;
        #pragma unroll
        for (int nt = 0; nt < 8; nt++) {
            int col = half*64 + nt*8 + 2*c;
            float b0 = s_bo[col], b1 = s_bo[col+1];
            float g0 = s_g[col], g1 = s_g[col+1];
            float e0 = s_be[col], e1 = s_be[col+1];
            int j = col >> 1;
            int ks = j >> 3;
            int ln = g*4 + (j & 3);
            int base = ((ks*8 + wid)*32 + ln)*4 + ((j & 4) ? 2 : 0);
            #pragma unroll
            for (int pr = 0; pr < 2; pr++) {
                int row = r0 + pr*8;
                if (row < NN) {
                    float mm = pr ? m1 : m0;
                    float rr = pr ? rs1 : rs0;
                    u32 hp = sAhi[base + pr], lp = sAlo[base + pr];
                    float t20 = bf_lo(hp) + bf_lo(lp);
                    float t21 = bf_hi(hp) + bf_hi(lp);
                    float z0 = fmaxf(acc[nt][pr*2]   + b0, 0.f);
                    float z1 = fmaxf(acc[nt][pr*2+1] + b1, 0.f);
                    float2 o;
                    o.x = t20 + (z0 - mm)*rr*g0 + e0;
                    o.y = t21 + (z1 - mm)*rr*g1 + e1;
                    *(float2*)(OUT + (size_t)row*128 + col) = o;
                }
            }
        }
    }
}

// ---------------- CSR construction ----------------
__global__ void zero_cnt_kernel() {
    int i = blockIdx.x*blockDim.x + threadIdx.x;
    if (i < TWO_N) g_cnt[i] = 0;
}

__global__ void hist_kernel(const int* __restrict__ et, const int* __restrict__ ex) {
    int i = blockIdx.x*blockDim.x + threadIdx.x;
    if (i < EE) {
        atomicAdd(&g_cnt[et[EE + i]], 1);
        atomicAdd(&g_cnt[NN + ex[EE + i]], 1);
    }
}

__global__ void scan1_kernel() {
    __shared__ int s[SCAN_B];
    int i = blockIdx.x*SCAN_B + threadIdx.x;
    int v = (i < TWO_N) ? g_cnt[i] : 0;
    s[threadIdx.x] = v;
    __syncthreads();
    #pragma unroll
    for (int d = 1; d < SCAN_B; d <<= 1) {
        int tv = (threadIdx.x >= d) ? s[threadIdx.x - d] : 0;
        __syncthreads();
        s[threadIdx.x] += tv;
        __syncthreads();
    }
    if (i < TWO_N) g_off[i + 1] = s[threadIdx.x];
    if (threadIdx.x == SCAN_B - 1) g_bsum[blockIdx.x] = s[SCAN_B - 1];
}

__global__ void scan2_kernel() {
    __shared__ int s[256];
    int v = (threadIdx.x < NSB) ? g_bsum[threadIdx.x] : 0;
    s[threadIdx.x] = v;
    __syncthreads();
    #pragma unroll
    for (int d = 1; d < 256; d <<= 1) {
        int tv = (threadIdx.x >= d) ? s[threadIdx.x - d] : 0;
        __syncthreads();
        s[threadIdx.x] += tv;
        __syncthreads();
    }
    if (threadIdx.x < NSB) g_bsum[threadIdx.x] = s[threadIdx.x] - v;
}

__global__ void scan3_kernel() {
    int i = blockIdx.x*blockDim.x + threadIdx.x;
    if (i == 0) { g_off[0] = 0; g_cnt[0] = 0; }
    else if (i <= TWO_N) {
        int v = g_off[i] + g_bsum[(i - 1) / SCAN_B];
        g_off[i] = v;
        if (i < TWO_N) g_cnt[i] = v;
    }
}

__global__ void fill_kernel(const int* __restrict__ et, const int* __restrict__ ex) {
    int i = blockIdx.x*blockDim.x + threadIdx.x;
    if (i < EE) {
        int p = atomicAdd(&g_cnt[et[EE + i]], 1);
        g_col[p] = et[i];
        int q = atomicAdd(&g_cnt[NN + ex[EE + i]], 1);
        g_col[q] = ex[i];
    }
}

// ---------------- aggregation: warp per destination node ----------------
__global__ void agg_kernel(const float* __restrict__ x, const float* __restrict__ t,
                           float* __restrict__ ua, float* __restrict__ ub) {
    int warp = (blockIdx.x*blockDim.x + threadIdx.x) >> 5;
    int lane = threadIdx.x & 31;
    if (warp >= NN) return;
    const float4* t4 = (const float4*)t;
    const float4* x4 = (const float4*)x;

    float4 base = t4[warp*32 + lane];
    float4 aA = base, aB = base;

    {
        int e = g_off[warp], eE = g_off[warp + 1];
        for (; e + 3 < eE; e += 4) {
            int s0 = g_col[e], s1 = g_col[e+1], s2 = g_col[e+2], s3 = g_col[e+3];
            float4 v0 = t4[s0*32 + lane];
            float4 v1 = t4[s1*32 + lane];
            float4 v2 = t4[s2*32 + lane];
            float4 v3 = t4[s3*32 + lane];
            aA.x += v0.x + v1.x + v2.x + v3.x;
            aA.y += v0.y + v1.y + v2.y + v3.y;
            aA.z += v0.z + v1.z + v2.z + v3.z;
            aA.w += v0.w + v1.w + v2.w + v3.w;
        }
        for (; e < eE; e++) {
            int s0 = g_col[e];
            float4 v0 = t4[s0*32 + lane];
            aA.x += v0.x; aA.y += v0.y; aA.z += v0.z; aA.w += v0.w;
        }
    }
    {
        int e = g_off[NN + warp], eE = g_off[NN + warp + 1];
        for (; e + 3 < eE; e += 4) {
            int s0 = g_col[e], s1 = g_col[e+1], s2 = g_col[e+2], s3 = g_col[e+3];
            float4 v0 = x4[s0*32 + lane];
            float4 v1 = x4[s1*32 + lane];
            float4 v2 = x4[s2*32 + lane];
            float4 v3 = x4[s3*32 + lane];
            aB.x += v0.x + v1.x + v2.x + v3.x;
            aB.y += v0.y + v1.y + v2.y + v3.y;
            aB.z += v0.z + v1.z + v2.z + v3.z;
            aB.w += v0.w + v1.w + v2.w + v3.w;
        }
        for (; e < eE; e++) {
            int s0 = g_col[e];
            float4 v0 = x4[s0*32 + lane];
            aB.x += v0.x; aB.y += v0.y; aB.z += v0.z; aB.w += v0.w;
        }
    }

    ((float4*)ua)[warp*32 + lane] = aA;
    ((float4*)ub)[warp*32 + lane] = aB;
}

// ---------------- launcher ----------------
extern "C" void kernel_launch(void* const* d_in, const int* in_sizes, int n_in,
                              void* d_out, int out_size) {
    const float* x   = (const float*)d_in[0];
    const float* t   = (const float*)d_in[1];
    const int*   et  = (const int*)d_in[2];
    const int*   ex  = (const int*)d_in[3];
    const float* W1a = (const float*)d_in[4];
    const float* b1a = (const float*)d_in[5];
    const float* W2a = (const float*)d_in[6];
    const float* b2a = (const float*)d_in[7];
    const float* W1b = (const float*)d_in[8];
    const float* b1b = (const float*)d_in[9];
    const float* W2b = (const float*)d_in[10];
    const float* b2b = (const float*)d_in[11];
    const float* Wo  = (const float*)d_in[12];
    const float* bo  = (const float*)d_in[13];
    const float* lng = (const float*)d_in[14];
    const float* lnb = (const float*)d_in[15];
    const float* Wf1 = (const float*)d_in[16];
    const float* bf1 = (const float*)d_in[17];
    const float* Wf2 = (const float*)d_in[18];
    const float* bf2 = (const float*)d_in[19];
    float* out = (float*)d_out;

    float *pua, *pub;
    cudaGetSymbolAddress((void**)&pua, g_ua);
    cudaGetSymbolAddress((void**)&pub, g_ub);

    cudaFuncSetAttribute(fc_x_mm,    cudaFuncAttributeMaxDynamicSharedMemorySize, SMEM_MM);
    cudaFuncSetAttribute(fused_t_mm, cudaFuncAttributeMaxDynamicSharedMemorySize, SMEM_MM);

    // fork: fc_x on a side stream overlaps the CSR+agg chain
    cudaStream_t side;
    cudaStreamCreateWithFlags(&side, cudaStreamNonBlocking);
    cudaEvent_t eFork, eJoin;
    cudaEventCreateWithFlags(&eFork, cudaEventDisableTiming);
    cudaEventCreateWithFlags(&eJoin, cudaEventDisableTiming);

    cudaEventRecord(eFork, 0);
    cudaStreamWaitEvent(side, eFork, 0);

    fc_x_mm<<<NBLK_MM, MMT, SMEM_MM, side>>>(x, Wf1, bf1, Wf2, bf2, out);
    cudaEventRecord(eJoin, side);

    zero_cnt_kernel<<<(TWO_N + 1023)/1024, 1024>>>();
    hist_kernel<<<(EE + 255)/256, 256>>>(et, ex);
    scan1_kernel<<<NSB, SCAN_B>>>();
    scan2_kernel<<<1, 256>>>();
    scan3_kernel<<<(TWO_N + 1 + 255)/256, 256>>>();
    fill_kernel<<<(EE + 255)/256, 256>>>(et, ex);
    agg_kernel<<<(NN + 7)/8, 256>>>(x, t, pua, pub);

    cudaStreamWaitEvent(0, eJoin, 0);
    fused_t_mm<<<NBLK_MM, MMT, SMEM_MM>>>(pua, pub, t,
        W1a, b1a, W2a, b2a, W1b, b1b, W2b, b2b,
        Wo, bo, lng, lnb, out + (size_t)NN*DD);

    cudaEventDestroy(eFork);
    cudaEventDestroy(eJoin);
    cudaStreamDestroy(side);
}

// round 13
// speedup vs baseline: 1.9313x; 1.3108x over previous
#include <cuda_runtime.h>

typedef unsigned long long ull;
typedef unsigned int u32;

#define NN 50000
#define DD 128
#define EE 1600000
#define TWO_N (2*NN)
#define SCAN_B 512
#define NSB ((TWO_N + SCAN_B - 1)/SCAN_B)
#define MT 128
#define NBLK_MM ((NN + MT - 1)/MT)   // 391
#define MMT 256                       // threads (8 warps)

// smem map (bytes): A frags hi/lo, B frags, biases
#define S_AHI 0
#define S_ALO 32768
#define S_B   65536
#define S_BIAS 98304
#define SMEM_MM 102400

// weight-fragment layer indices
#define WI_W1A 0
#define WI_W2A 1
#define WI_W1B 2
#define WI_W2B 3
#define WI_WO  4
#define WI_WF1 5
#define WI_WF2 6

// ---------------- scratch ----------------
__device__ int   g_cnt[TWO_N];
__device__ int   g_off[TWO_N + 1];
__device__ int   g_bsum[NSB];
__device__ int   g_col[2*EE];
__device__ float g_ua[NN*DD];
__device__ float g_ub[NN*DD];
__device__ uint4 g_wfrag[7*4096];    // [w][half][2048] fragment-order weights

// ---------------- bf16 helpers ----------------
__device__ __forceinline__ u32 pkbf(float lo, float hi) {
    u32 r; asm("cvt.rn.bf16x2.f32 %0, %1, %2;" : "=r"(r) : "f"(hi), "f"(lo)); return r;
}
__device__ __forceinline__ float bf_lo(u32 p) { return __uint_as_float(p << 16); }
__device__ __forceinline__ float bf_hi(u32 p) { return __uint_as_float(p & 0xffff0000u); }

#define MMA4(d, a0, a1, a2, a3, b0, b1) \
    asm volatile("mma.sync.aligned.m16n8k16.row.col.f32.bf16.bf16.f32 " \
        "{%0,%1,%2,%3}, {%4,%5,%6,%7}, {%8,%9}, {%0,%1,%2,%3};" \
        : "+f"((d)[0]), "+f"((d)[1]), "+f"((d)[2]), "+f"((d)[3]) \
        : "r"(a0), "r"(a1), "r"(a2), "r"(a3), "r"(b0), "r"(b1))

// ---------------- one-time weight fragment prep ----------------
__global__ void prep_w(const float* __restrict__ W1a, const float* __restrict__ W2a,
                       const float* __restrict__ W1b, const float* __restrict__ W2b,
                       const float* __restrict__ Wo,  const float* __restrict__ Wf1,
                       const float* __restrict__ Wf2) {
    int idx = blockIdx.x*blockDim.x + threadIdx.x;
    if (idx >= 7*4096) return;
    const float* Ws[7] = {W1a, W2a, W1b, W2b, Wo, Wf1, Wf2};
    int w = idx >> 12;
    int rem = idx & 4095;
    int half = rem >> 11;
    int s = rem & 2047;                  // (ks*8+nt)*32+lane
    int lane = s & 31, nt = (s >> 5) & 7, ks = s >> 8;
    int g = lane >> 2, c = lane & 3;
    const float* W = Ws[w];
    int n = half*64 + nt*8 + g;
    int k0 = ks*16 + 2*c;
    float w00 = W[(size_t)k0*128 + n];
    float w01 = W[(size_t)(k0+1)*128 + n];
    float w10 = W[(size_t)(k0+8)*128 + n];
    float w11 = W[(size_t)(k0+9)*128 + n];
    u32 bh0 = pkbf(w00, w01);
    u32 bh1 = pkbf(w10, w11);
    u32 bl0 = pkbf(w00 - bf_lo(bh0), w01 - bf_hi(bh0));
    u32 bl1 = pkbf(w10 - bf_lo(bh1), w11 - bf_hi(bh1));
    g_wfrag[idx] = make_uint4(bh0, bh1, bl0, bl1);
}

// ---------------- fragment staging ----------------
__device__ __forceinline__ void stage_A(u32* sAhi, u32* sAlo, const float* A, int row0) {
    for (int idx = threadIdx.x; idx < 128*64; idx += MMT) {
        int r = idx >> 6, j = idx & 63;
        int row = row0 + r;
        float v0 = 0.f, v1 = 0.f;
        if (row < NN) {
            float2 vv = *(const float2*)(A + (size_t)row*128 + 2*j);
            v0 = vv.x; v1 = vv.y;
        }
        u32 hp = pkbf(v0, v1);
        u32 lp = pkbf(v0 - bf_lo(hp), v1 - bf_hi(hp));
        int ks = j >> 3;
        int reg = ((r >> 3) & 1) | ((j & 4) ? 2 : 0);
        int ln  = (r & 7)*4 + (j & 3);
        int mt  = r >> 4;
        int o = ((ks*8 + mt)*32 + ln)*4 + reg;
        sAhi[o] = hp; sAlo[o] = lp;
    }
}

// stage one N-half of prefab frags: coalesced 32KB copy
__device__ __forceinline__ void stage_W(u32* sB, const uint4* __restrict__ gw) {
    uint4* dst = (uint4*)sB;
    #pragma unroll
    for (int i = threadIdx.x; i < 2048; i += MMT) dst[i] = gw[i];
}

__device__ __forceinline__ void mma_half(const u32* sAhi, const u32* sAlo, const u32* sB,
                                         int wid, int lane, float acc[8][4]) {
    #pragma unroll
    for (int nt = 0; nt < 8; nt++)
        #pragma unroll
        for (int q = 0; q < 4; q++) acc[nt][q] = 0.f;
    #pragma unroll
    for (int ks = 0; ks < 8; ks++) {
        uint4 ah = *(const uint4*)(sAhi + ((ks*8 + wid)*32 + lane)*4);
        uint4 al = *(const uint4*)(sAlo + ((ks*8 + wid)*32 + lane)*4);
        #pragma unroll
        for (int nt = 0; nt < 8; nt++) {
            uint4 b = *(const uint4*)(sB + ((ks*8 + nt)*32 + lane)*4);
            MMA4(acc[nt], ah.x, ah.y, ah.z, ah.w, b.x, b.y);
            MMA4(acc[nt], al.x, al.y, al.z, al.w, b.x, b.y);
            MMA4(acc[nt], ah.x, ah.y, ah.z, ah.w, b.z, b.w);
        }
    }
}

// full layer; gw = &g_wfrag[wi*4096]
__device__ __forceinline__ void layer(u32* sAhi, u32* sAlo, u32* sB,
                                      const uint4* __restrict__ gw,
                                      int wid, int lane,
                                      float acc0[8][4], float acc1[8][4]) {
    __syncthreads();
    stage_W(sB, gw);
    __syncthreads();
    mma_half(sAhi, sAlo, sB, wid, lane, acc0);
    __syncthreads();
    stage_W(sB, gw + 2048);
    __syncthreads();
    mma_half(sAhi, sAlo, sB, wid, lane, acc1);
}

__device__ __forceinline__ void write_H(u32* sAhi, u32* sAlo,
                                        float acc0[8][4], float acc1[8][4],
                                        const float* bias, int wid, int lane) {
    int g = lane >> 2, c = lane & 3;
    #pragma unroll
    for (int half = 0; half < 2; half++) {
        float (*acc)[4] = half ? acc1 : acc0;
        #pragma unroll
        for (int nt = 0; nt < 8; nt++) {
            int col = half*64 + nt*8 + 2*c;
            float b0 = bias[col], b1 = bias[col+1];
            int j = col >> 1;
            int ks = j >> 3;
            int ln = g*4 + (j & 3);
            int base = ((ks*8 + wid)*32 + ln)*4 + ((j & 4) ? 2 : 0);
            #pragma unroll
            for (int pr = 0; pr < 2; pr++) {
                float v0 = fmaxf(acc[nt][pr*2]   + b0, 0.f);
                float v1 = fmaxf(acc[nt][pr*2+1] + b1, 0.f);
                u32 hp = pkbf(v0, v1);
                u32 lp = pkbf(v0 - bf_lo(hp), v1 - bf_hi(hp));
                sAhi[base + pr] = hp;
                sAlo[base + pr] = lp;
            }
        }
    }
}

// ================= fc_x: x + relu(x@Wf1+bf1)@Wf2 + bf2 =================
__global__ __launch_bounds__(MMT, 2) void fc_x_mm(
    const float* __restrict__ X,
    const uint4* __restrict__ gwf,
    const float* __restrict__ B1, const float* __restrict__ B2,
    float* __restrict__ OUT)
{
    extern __shared__ char smc[];
    u32* sAhi = (u32*)(smc + S_AHI);
    u32* sAlo = (u32*)(smc + S_ALO);
    u32* sB   = (u32*)(smc + S_B);
    float* sb1 = (float*)(smc + S_BIAS);
    float* sb2 = (float*)(smc + S_BIAS + 512);

    const int tid = threadIdx.x;
    const int wid = tid >> 5, lane = tid & 31;
    const int row0 = blockIdx.x * MT;
    if (tid < 128) { sb1[tid] = B1[tid]; sb2[tid] = B2[tid]; }
    stage_A(sAhi, sAlo, X, row0);

    float acc0[8][4], acc1[8][4];
    layer(sAhi, sAlo, sB, gwf + WI_WF1*4096, wid, lane, acc0, acc1);
    write_H(sAhi, sAlo, acc0, acc1, sb1, wid, lane);
    layer(sAhi, sAlo, sB, gwf + WI_WF2*4096, wid, lane, acc0, acc1);

    int g = lane >> 2, c = lane & 3;
    int r0 = row0 + wid*16 + g;
    #pragma unroll
    for (int half = 0; half < 2; half++) {
        float (*acc)[4] = half ? acc1 : acc0;
        #pragma unroll
        for (int nt = 0; nt < 8; nt++) {
            int col = half*64 + nt*8 + 2*c;
            float b0 = sb2[col], b1 = sb2[col+1];
            #pragma unroll
            for (int pr = 0; pr < 2; pr++) {
                int row = r0 + pr*8;
                if (row < NN) {
                    float2 xv = *(const float2*)(X + (size_t)row*128 + col);
                    float2 o;
                    o.x = xv.x + acc[nt][pr*2]   + b0;
                    o.y = xv.y + acc[nt][pr*2+1] + b1;
                    *(float2*)(OUT + (size_t)row*128 + col) = o;
                }
            }
        }
    }
}

// ================= fused t-branch =================
__global__ __launch_bounds__(MMT, 2) void fused_t_mm(
    float* __restrict__ ua, const float* __restrict__ ub, const float* __restrict__ t,
    const uint4* __restrict__ gwf,
    const float* __restrict__ b1a, const float* __restrict__ b2a,
    const float* __restrict__ b1b, const float* __restrict__ b2b,
    const float* __restrict__ bo,
    const float* __restrict__ lng, const float* __restrict__ lnb,
    float* __restrict__ OUT)
{
    extern __shared__ char smc[];
    u32* sAhi = (u32*)(smc + S_AHI);
    u32* sAlo = (u32*)(smc + S_ALO);
    u32* sB   = (u32*)(smc + S_B);
    float* s_b1a = (float*)(smc + S_BIAS);
    float* s_b2a = (float*)(smc + S_BIAS + 512);
    float* s_b1b = (float*)(smc + S_BIAS + 1024);
    float* s_b2b = (float*)(smc + S_BIAS + 1536);
    float* s_bo  = (float*)(smc + S_BIAS + 2048);
    float* s_g   = (float*)(smc + S_BIAS + 2560);
    float* s_be  = (float*)(smc + S_BIAS + 3072);

    const int tid = threadIdx.x;
    const int wid = tid >> 5, lane = tid & 31;
    const int g = lane >> 2, c = lane & 3;
    const int row0 = blockIdx.x * MT;
    const int r0 = row0 + wid*16 + g;

    if (tid < 128) {
        s_b1a[tid] = b1a[tid]; s_b2a[tid] = b2a[tid];
        s_b1b[tid] = b1b[tid]; s_b2b[tid] = b2b[tid];
        s_bo[tid]  = bo[tid];  s_g[tid]   = lng[tid]; s_be[tid] = lnb[tid];
    }
    stage_A(sAhi, sAlo, ua, row0);

    float acc0[8][4], acc1[8][4];

    // ---- gin_a ----
    layer(sAhi, sAlo, sB, gwf + WI_W1A*4096, wid, lane, acc0, acc1);
    write_H(sAhi, sAlo, acc0, acc1, s_b1a, wid, lane);
    layer(sAhi, sAlo, sB, gwf + WI_W2A*4096, wid, lane, acc0, acc1);

    // partial = t + ga + b2a -> g_ua
    #pragma unroll
    for (int half = 0; half < 2; half++) {
        float (*acc)[4] = half ? acc1 : acc0;
        #pragma unroll
        for (int nt = 0; nt < 8; nt++) {
            int col = half*64 + nt*8 + 2*c;
            float b0 = s_b2a[col], b1 = s_b2a[col+1];
            #pragma unroll
            for (int pr = 0; pr < 2; pr++) {
                int row = r0 + pr*8;
                if (row < NN) {
                    float2 tv = *(const float2*)(t + (size_t)row*128 + col);
                    float2 o;
                    o.x = tv.x + acc[nt][pr*2]   + b0;
                    o.y = tv.y + acc[nt][pr*2+1] + b1;
                    *(float2*)(ua + (size_t)row*128 + col) = o;
                }
            }
        }
    }

    // ---- gin_b ----
    __syncthreads();
    stage_A(sAhi, sAlo, ub, row0);
    layer(sAhi, sAlo, sB, gwf + WI_W1B*4096, wid, lane, acc0, acc1);
    write_H(sAhi, sAlo, acc0, acc1, s_b1b, wid, lane);
    layer(sAhi, sAlo, sB, gwf + WI_W2B*4096, wid, lane, acc0, acc1);

    // t2 = relu(partial + gb + b2b) -> A frags (input of Wo layer)
    #pragma unroll
    for (int half = 0; half < 2; half++) {
        float (*acc)[4] = half ? acc1 : acc0;
        #pragma unroll
        for (int nt = 0; nt < 8; nt++) {
            int col = half*64 + nt*8 + 2*c;
            float b0 = s_b2b[col], b1 = s_b2b[col+1];
            int j = col >> 1;
            int ks = j >> 3;
            int ln = g*4 + (j & 3);
            int base = ((ks*8 + wid)*32 + ln)*4 + ((j & 4) ? 2 : 0);
            #pragma unroll
            for (int pr = 0; pr < 2; pr++) {
                int row = r0 + pr*8;
                float p0 = 0.f, p1 = 0.f;
                if (row < NN) {
                    float2 pv = *(const float2*)(ua + (size_t)row*128 + col);
                    p0 = pv.x; p1 = pv.y;
                }
                float v0 = fmaxf(p0 + acc[nt][pr*2]   + b0, 0.f);
                float v1 = fmaxf(p1 + acc[nt][pr*2+1] + b1, 0.f);
                u32 hp = pkbf(v0, v1);
                u32 lp = pkbf(v0 - bf_lo(hp), v1 - bf_hi(hp));
                sAhi[base + pr] = hp;
                sAlo[base + pr] = lp;
            }
        }
    }

    // ---- out branch: z = relu(t2@Wo+bo); OUT = t2 + LN(z) ----
    layer(sAhi, sAlo, sB, gwf + WI_WO*4096, wid, lane, acc0, acc1);

    float s0 = 0.f, q0 = 0.f, s1 = 0.f, q1 = 0.f;
    #pragma unroll
    for (int half = 0; half < 2; half++) {
        float (*acc)[4] = half ? acc1 : acc0;
        #pragma unroll
        for (int nt = 0; nt < 8; nt++) {
            int col = half*64 + nt*8 + 2*c;
            float b0 = s_bo[col], b1 = s_bo[col+1];
            float z00 = fmaxf(acc[nt][0] + b0, 0.f);
            float z01 = fmaxf(acc[nt][1] + b1, 0.f);
            float z10 = fmaxf(acc[nt][2] + b0, 0.f);
            float z11 = fmaxf(acc[nt][3] + b1, 0.f);
            s0 += z00 + z01; q0 += z00*z00 + z01*z01;
            s1 += z10 + z11; q1 += z10*z10 + z11*z11;
        }
    }
    #pragma unroll
    for (int d = 1; d <= 2; d <<= 1) {
        s0 += __shfl_xor_sync(0xffffffffu, s0, d);
        q0 += __shfl_xor_sync(0xffffffffu, q0, d);
        s1 += __shfl_xor_sync(0xffffffffu, s1, d);
        q1 += __shfl_xor_sync(0xffffffffu, q1, d);
    }
    float m0 = s0*(1.f/128.f), m1 = s1*(1.f/128.f);
    float rs0 = rsqrtf(q0*(1.f/128.f) - m0*m0 + 1e-5f);
    float rs1 = rsqrtf(q1*(1.f/128.f) - m1*m1 + 1e-5f);

    #pragma unroll
    for (int half = 0; half < 2; half++) {
        float (*acc)[4] = half ? acc1 : acc0;
        #pragma unroll
        for (int nt = 0; nt < 8; nt++) {
            int col = half*64 + nt*8 + 2*c;
            float b0 = s_bo[col], b1 = s_bo[col+1];
            float g0 = s_g[col], g1 = s_g[col+1];
            float e0 = s_be[col], e1 = s_be[col+1];
            int j = col >> 1;
            int ks = j >> 3;
            int ln = g*4 + (j & 3);
            int base = ((ks*8 + wid)*32 + ln)*4 + ((j & 4) ? 2 : 0);
            #pragma unroll
            for (int pr = 0; pr < 2; pr++) {
                int row = r0 + pr*8;
                if (row < NN) {
                    float mm = pr ? m1 : m0;
                    float rr = pr ? rs1 : rs0;
                    u32 hp = sAhi[base + pr], lp = sAlo[base + pr];
                    float t20 = bf_lo(hp) + bf_lo(lp);
                    float t21 = bf_hi(hp) + bf_hi(lp);
                    float z0 = fmaxf(acc[nt][pr*2]   + b0, 0.f);
                    float z1 = fmaxf(acc[nt][pr*2+1] + b1, 0.f);
                    float2 o;
                    o.x = t20 + (z0 - mm)*rr*g0 + e0;
                    o.y = t21 + (z1 - mm)*rr*g1 + e1;
                    *(float2*)(OUT + (size_t)row*128 + col) = o;
                }
            }
        }
    }
}

// ---------------- CSR construction ----------------
__global__ void zero_cnt_kernel() {
    int i = blockIdx.x*blockDim.x + threadIdx.x;
    if (i < TWO_N) g_cnt[i] = 0;
}

__global__ void hist_kernel(const int* __restrict__ et, const int* __restrict__ ex) {
    int i = blockIdx.x*blockDim.x + threadIdx.x;
    if (i < EE) {
        atomicAdd(&g_cnt[et[EE + i]], 1);
        atomicAdd(&g_cnt[NN + ex[EE + i]], 1);
    }
}

__global__ void scan1_kernel() {
    __shared__ int s[SCAN_B];
    int i = blockIdx.x*SCAN_B + threadIdx.x;
    int v = (i < TWO_N) ? g_cnt[i] : 0;
    s[threadIdx.x] = v;
    __syncthreads();
    #pragma unroll
    for (int d = 1; d < SCAN_B; d <<= 1) {
        int tv = (threadIdx.x >= d) ? s[threadIdx.x - d] : 0;
        __syncthreads();
        s[threadIdx.x] += tv;
        __syncthreads();
    }
    if (i < TWO_N) g_off[i + 1] = s[threadIdx.x];
    if (threadIdx.x == SCAN_B - 1) g_bsum[blockIdx.x] = s[SCAN_B - 1];
}

__global__ void scan2_kernel() {
    __shared__ int s[256];
    int v = (threadIdx.x < NSB) ? g_bsum[threadIdx.x] : 0;
    s[threadIdx.x] = v;
    __syncthreads();
    #pragma unroll
    for (int d = 1; d < 256; d <<= 1) {
        int tv = (threadIdx.x >= d) ? s[threadIdx.x - d] : 0;
        __syncthreads();
        s[threadIdx.x] += tv;
        __syncthreads();
    }
    if (threadIdx.x < NSB) g_bsum[threadIdx.x] = s[threadIdx.x] - v;
}

__global__ void scan3_kernel() {
    int i = blockIdx.x*blockDim.x + threadIdx.x;
    if (i == 0) { g_off[0] = 0; g_cnt[0] = 0; }
    else if (i <= TWO_N) {
        int v = g_off[i] + g_bsum[(i - 1) / SCAN_B];
        g_off[i] = v;
        if (i < TWO_N) g_cnt[i] = v;
    }
}

__global__ void fill_kernel(const int* __restrict__ et, const int* __restrict__ ex) {
    int i = blockIdx.x*blockDim.x + threadIdx.x;
    if (i < EE) {
        int p = atomicAdd(&g_cnt[et[EE + i]], 1);
        g_col[p] = et[i];
        int q = atomicAdd(&g_cnt[NN + ex[EE + i]], 1);
        g_col[q] = ex[i];
    }
}

// ---------------- aggregation: warp per destination node ----------------
__global__ void agg_kernel(const float* __restrict__ x, const float* __restrict__ t,
                           float* __restrict__ ua, float* __restrict__ ub) {
    int warp = (blockIdx.x*blockDim.x + threadIdx.x) >> 5;
    int lane = threadIdx.x & 31;
    if (warp >= NN) return;
    const float4* t4 = (const float4*)t;
    const float4* x4 = (const float4*)x;

    float4 base = t4[warp*32 + lane];
    float4 aA = base, aB = base;

    {
        int e = g_off[warp], eE = g_off[warp + 1];
        for (; e + 3 < eE; e += 4) {
            int s0 = g_col[e], s1 = g_col[e+1], s2 = g_col[e+2], s3 = g_col[e+3];
            float4 v0 = t4[s0*32 + lane];
            float4 v1 = t4[s1*32 + lane];
            float4 v2 = t4[s2*32 + lane];
            float4 v3 = t4[s3*32 + lane];
            aA.x += v0.x + v1.x + v2.x + v3.x;
            aA.y += v0.y + v1.y + v2.y + v3.y;
            aA.z += v0.z + v1.z + v2.z + v3.z;
            aA.w += v0.w + v1.w + v2.w + v3.w;
        }
        for (; e < eE; e++) {
            int s0 = g_col[e];
            float4 v0 = t4[s0*32 + lane];
            aA.x += v0.x; aA.y += v0.y; aA.z += v0.z; aA.w += v0.w;
        }
    }
    {
        int e = g_off[NN + warp], eE = g_off[NN + warp + 1];
        for (; e + 3 < eE; e += 4) {
            int s0 = g_col[e], s1 = g_col[e+1], s2 = g_col[e+2], s3 = g_col[e+3];
            float4 v0 = x4[s0*32 + lane];
            float4 v1 = x4[s1*32 + lane];
            float4 v2 = x4[s2*32 + lane];
            float4 v3 = x4[s3*32 + lane];
            aB.x += v0.x + v1.x + v2.x + v3.x;
            aB.y += v0.y + v1.y + v2.y + v3.y;
            aB.z += v0.z + v1.z + v2.z + v3.z;
            aB.w += v0.w + v1.w + v2.w + v3.w;
        }
        for (; e < eE; e++) {
            int s0 = g_col[e];
            float4 v0 = x4[s0*32 + lane];
            aB.x += v0.x; aB.y += v0.y; aB.z += v0.z; aB.w += v0.w;
        }
    }

    ((float4*)ua)[warp*32 + lane] = aA;
    ((float4*)ub)[warp*32 + lane] = aB;
}

// ---------------- launcher ----------------
extern "C" void kernel_launch(void* const* d_in, const int* in_sizes, int n_in,
                              void* d_out, int out_size) {
    const float* x   = (const float*)d_in[0];
    const float* t   = (const float*)d_in[1];
    const int*   et  = (const int*)d_in[2];
    const int*   ex  = (const int*)d_in[3];
    const float* W1a = (const float*)d_in[4];
    const float* b1a = (const float*)d_in[5];
    const float* W2a = (const float*)d_in[6];
    const float* b2a = (const float*)d_in[7];
    const float* W1b = (const float*)d_in[8];
    const float* b1b = (const float*)d_in[9];
    const float* W2b = (const float*)d_in[10];
    const float* b2b = (const float*)d_in[11];
    const float* Wo  = (const float*)d_in[12];
    const float* bo  = (const float*)d_in[13];
    const float* lng = (const float*)d_in[14];
    const float* lnb = (const float*)d_in[15];
    const float* Wf1 = (const float*)d_in[16];
    const float* bf1 = (const float*)d_in[17];
    const float* Wf2 = (const float*)d_in[18];
    const float* bf2 = (const float*)d_in[19];
    float* out = (float*)d_out;

    float *pua, *pub;
    uint4* pwf;
    cudaGetSymbolAddress((void**)&pua, g_ua);
    cudaGetSymbolAddress((void**)&pub, g_ub);
    cudaGetSymbolAddress((void**)&pwf, g_wfrag);

    cudaFuncSetAttribute(fc_x_mm,    cudaFuncAttributeMaxDynamicSharedMemorySize, SMEM_MM);
    cudaFuncSetAttribute(fused_t_mm, cudaFuncAttributeMaxDynamicSharedMemorySize, SMEM_MM);

    // one-time weight fragment prep (before fork: both branches depend on it)
    prep_w<<<(7*4096 + 255)/256, 256>>>(W1a, W2a, W1b, W2b, Wo, Wf1, Wf2);

    // fork: fc_x on a side stream overlaps the CSR+agg chain
    cudaStream_t side;
    cudaStreamCreateWithFlags(&side, cudaStreamNonBlocking);
    cudaEvent_t eFork, eJoin;
    cudaEventCreateWithFlags(&eFork, cudaEventDisableTiming);
    cudaEventCreateWithFlags(&eJoin, cudaEventDisableTiming);

    cudaEventRecord(eFork, 0);
    cudaStreamWaitEvent(side, eFork, 0);

    fc_x_mm<<<NBLK_MM, MMT, SMEM_MM, side>>>(x, pwf, bf1, bf2, out);
    cudaEventRecord(eJoin, side);

    zero_cnt_kernel<<<(TWO_N + 1023)/1024, 1024>>>();
    hist_kernel<<<(EE + 255)/256, 256>>>(et, ex);
    scan1_kernel<<<NSB, SCAN_B>>>();
    scan2_kernel<<<1, 256>>>();
    scan3_kernel<<<(TWO_N + 1 + 255)/256, 256>>>();
    fill_kernel<<<(EE + 255)/256, 256>>>(et, ex);
    agg_kernel<<<(NN + 7)/8, 256>>>(x, t, pua, pub);

    cudaStreamWaitEvent(0, eJoin, 0);
    fused_t_mm<<<NBLK_MM, MMT, SMEM_MM>>>(pua, pub, t, pwf,
        b1a, b2a, b1b, b2b, bo, lng, lnb, out + (size_t)NN*DD);

    cudaEventDestroy(eFork);
    cudaEventDestroy(eJoin);
    cudaStreamDestroy(side);
}